// round 4
// baseline (speedup 1.0000x reference)
#include <cuda_runtime.h>
#include <cuda_bf16.h>
#include <math.h>

#define MAXN 100000
#define MAXG 1000
#define D1 3
#define H  50
#define D3 15
#define D5 10
#define NC 6
#define EPS 1e-5f

#define TPB 256

typedef unsigned long long ull;

// -------- scratch (device globals) --------
__device__ float g_x2sum[MAXN * 16];
__device__ float g_gsum[MAXG * 16];
__device__ float g_z[MAXG * D5];
__device__ float g_zstat[2 * D5];

// -------- packed f32x2 helpers --------
__device__ __forceinline__ ull pack2(float a, float b) {
    ull r;
    asm("mov.b64 %0, {%1,%2};" : "=l"(r) : "f"(a), "f"(b));
    return r;
}
__device__ __forceinline__ void unpack2(ull v, float& a, float& b) {
    asm("mov.b64 {%0,%1}, %2;" : "=f"(a), "=f"(b) : "l"(v));
}
__device__ __forceinline__ void ffma2(ull& d, ull a, ull b) {
    asm("fma.rn.f32x2 %0, %1, %2, %0;" : "+l"(d) : "l"(a), "l"(b));
}
__device__ __forceinline__ ull relu2(ull v) {
    float a, b; unpack2(v, a, b);
    return pack2(fmaxf(a, 0.f), fmaxf(b, 0.f));
}

__device__ __forceinline__ void red_add_v4(float* dst, float a, float b, float c, float d) {
    asm volatile("red.global.add.v4.f32 [%0], {%1,%2,%3,%4};"
                 :: "l"(dst), "f"(a), "f"(b), "f"(c), "f"(d) : "memory");
}

// -------------------- zero scratch --------------------
__global__ void zero_kernel(int n_x2, int n_g) {
    int i = blockIdx.x * blockDim.x + threadIdx.x;
    int stride = gridDim.x * blockDim.x;
    for (int k = i; k < n_x2; k += stride) g_x2sum[k] = 0.f;
    for (int k = i; k < n_g;  k += stride) g_gsum[k]  = 0.f;
    if (i < 2 * D5) g_zstat[i] = 0.f;
}

// Shared layout (ull units, all bases even => 16B aligned)
#define OFF_EW1  0        // [9][50]   450
#define OFF_EB1  450      // 50
#define OFF_EW2  500      // [50][16]  800 (D3 padded to 16)
#define OFF_EB2  1300     // 16
#define OFF_NW1  1316     // [18][50]  900
#define OFF_NB1  2216     // 50
#define OFF_NW2  2266     // [50][16]  800
#define OFF_NB2  3066     // 16
#define S_ULL    3082

// -------------------- edge + node-message kernel --------------------
__global__ __launch_bounds__(TPB, 1)
void edge_kernel(const float* __restrict__ x, const int* __restrict__ ei,
                 const float* __restrict__ ea,
                 const float* __restrict__ ew1, const float* __restrict__ eb1,
                 const float* __restrict__ ew2, const float* __restrict__ eb2,
                 const float* __restrict__ nw1, const float* __restrict__ nb1,
                 const float* __restrict__ nw2, const float* __restrict__ nb2,
                 int E)
{
    __shared__ __align__(16) ull s[S_ULL];

    int tid = threadIdx.x;
    for (int i = tid; i < 450; i += TPB) { float w = ew1[i]; s[OFF_EW1 + i] = pack2(w, w); }
    for (int i = tid; i < H;   i += TPB) { float w = eb1[i]; s[OFF_EB1 + i] = pack2(w, w); }
    for (int i = tid; i < 800; i += TPB) {
        int k = i >> 4, j = i & 15;
        float w = (j < D3) ? ew2[k * D3 + j] : 0.f;
        s[OFF_EW2 + i] = pack2(w, w);
    }
    for (int i = tid; i < 16;  i += TPB) { float w = (i < D3) ? eb2[i] : 0.f; s[OFF_EB2 + i] = pack2(w, w); }
    for (int i = tid; i < 900; i += TPB) { float w = nw1[i]; s[OFF_NW1 + i] = pack2(w, w); }
    for (int i = tid; i < H;   i += TPB) { float w = nb1[i]; s[OFF_NB1 + i] = pack2(w, w); }
    for (int i = tid; i < 800; i += TPB) {
        int k = i >> 4, j = i & 15;
        float w = (j < D3) ? nw2[k * D3 + j] : 0.f;
        s[OFF_NW2 + i] = pack2(w, w);
    }
    for (int i = tid; i < 16;  i += TPB) { float w = (i < D3) ? nb2[i] : 0.f; s[OFF_NB2 + i] = pack2(w, w); }
    __syncthreads();

    const ulonglong2* sv = reinterpret_cast<const ulonglong2*>(s);

    int npairs = (E + 1) >> 1;
    for (int p = blockIdx.x * TPB + tid; p < npairs; p += gridDim.x * TPB) {
        int e0 = 2 * p;
        bool has2 = (e0 + 1 < E);
        int e1 = has2 ? e0 + 1 : e0;

        int2 rr, cc;
        if (has2) {
            rr = *reinterpret_cast<const int2*>(&ei[e0]);
            cc = *reinterpret_cast<const int2*>(&ei[E + e0]);
        } else {
            rr.x = rr.y = ei[e0];
            cc.x = cc.y = ei[E + e0];
        }
        int r0 = rr.x, r1 = rr.y, c0 = cc.x, c1 = cc.y;

        ull in[9];
        in[0] = pack2(__ldg(&x[3 * r0]),     __ldg(&x[3 * r1]));
        in[1] = pack2(__ldg(&x[3 * r0 + 1]), __ldg(&x[3 * r1 + 1]));
        in[2] = pack2(__ldg(&x[3 * r0 + 2]), __ldg(&x[3 * r1 + 2]));
        in[3] = pack2(__ldg(&x[3 * c0]),     __ldg(&x[3 * c1]));
        in[4] = pack2(__ldg(&x[3 * c0 + 1]), __ldg(&x[3 * c1 + 1]));
        in[5] = pack2(__ldg(&x[3 * c0 + 2]), __ldg(&x[3 * c1 + 2]));
        if (has2) {
            float2 a01 = *reinterpret_cast<const float2*>(&ea[3 * e0]);
            float2 a23 = *reinterpret_cast<const float2*>(&ea[3 * e0 + 2]);
            float2 a45 = *reinterpret_cast<const float2*>(&ea[3 * e0 + 4]);
            in[6] = pack2(a01.x, a23.y);
            in[7] = pack2(a01.y, a45.x);
            in[8] = pack2(a23.x, a45.y);
        } else {
            in[6] = pack2(ea[3 * e0],     ea[3 * e0]);
            in[7] = pack2(ea[3 * e0 + 1], ea[3 * e0 + 1]);
            in[8] = pack2(ea[3 * e0 + 2], ea[3 * e0 + 2]);
        }

        // ---- edge MLP layer 1: 9 -> 50, ReLU ----
        ull h[H];
        #pragma unroll
        for (int j = 0; j < H; j += 2) {
            ulonglong2 b = sv[(OFF_EB1 + j) >> 1];
            h[j] = b.x; h[j + 1] = b.y;
        }
        #pragma unroll
        for (int k = 0; k < 9; k++) {
            ull a = in[k];
            #pragma unroll
            for (int j = 0; j < H; j += 2) {
                ulonglong2 w = sv[(OFF_EW1 + k * H + j) >> 1];
                ffma2(h[j], a, w.x);
                ffma2(h[j + 1], a, w.y);
            }
        }
        #pragma unroll
        for (int j = 0; j < H; j++) h[j] = relu2(h[j]);

        // ---- edge MLP layer 2: 50 -> 15 (stride 16) ----
        ull e2[16];
        #pragma unroll
        for (int j = 0; j < 16; j += 2) {
            ulonglong2 b = sv[(OFF_EB2 + j) >> 1];
            e2[j] = b.x; e2[j + 1] = b.y;
        }
        #pragma unroll
        for (int k = 0; k < H; k++) {
            ull a = h[k];
            #pragma unroll
            for (int j = 0; j < 16; j += 2) {
                ulonglong2 w = sv[(OFF_EW2 + k * 16 + j) >> 1];
                ffma2(e2[j], a, w.x);
                ffma2(e2[j + 1], a, w.y);
            }
        }

        // ---- node MLP layer 1: [x[col](3), e2(15)] -> 50, ReLU ----
        ull g[H];
        #pragma unroll
        for (int j = 0; j < H; j += 2) {
            ulonglong2 b = sv[(OFF_NB1 + j) >> 1];
            g[j] = b.x; g[j + 1] = b.y;
        }
        #pragma unroll
        for (int k = 0; k < 3; k++) {
            ull a = in[3 + k];
            #pragma unroll
            for (int j = 0; j < H; j += 2) {
                ulonglong2 w = sv[(OFF_NW1 + k * H + j) >> 1];
                ffma2(g[j], a, w.x);
                ffma2(g[j + 1], a, w.y);
            }
        }
        #pragma unroll
        for (int k = 0; k < D3; k++) {
            ull a = e2[k];
            #pragma unroll
            for (int j = 0; j < H; j += 2) {
                ulonglong2 w = sv[(OFF_NW1 + (3 + k) * H + j) >> 1];
                ffma2(g[j], a, w.x);
                ffma2(g[j + 1], a, w.y);
            }
        }
        #pragma unroll
        for (int j = 0; j < H; j++) g[j] = relu2(g[j]);

        // ---- node MLP layer 2: 50 -> 15 (stride 16) ----
        ull m[16];
        #pragma unroll
        for (int j = 0; j < 16; j += 2) {
            ulonglong2 b = sv[(OFF_NB2 + j) >> 1];
            m[j] = b.x; m[j + 1] = b.y;
        }
        #pragma unroll
        for (int k = 0; k < H; k++) {
            ull a = g[k];
            #pragma unroll
            for (int j = 0; j < 16; j += 2) {
                ulonglong2 w = sv[(OFF_NW2 + k * 16 + j) >> 1];
                ffma2(m[j], a, w.x);
                ffma2(m[j + 1], a, w.y);
            }
        }

        float ma[16], mb[16];
        #pragma unroll
        for (int j = 0; j < D3; j++) unpack2(m[j], ma[j], mb[j]);
        ma[15] = 1.0f; mb[15] = 1.0f;

        float* d0 = g_x2sum + (size_t)r0 * 16;
        red_add_v4(d0,      ma[0],  ma[1],  ma[2],  ma[3]);
        red_add_v4(d0 + 4,  ma[4],  ma[5],  ma[6],  ma[7]);
        red_add_v4(d0 + 8,  ma[8],  ma[9],  ma[10], ma[11]);
        red_add_v4(d0 + 12, ma[12], ma[13], ma[14], ma[15]);
        if (has2) {
            float* d1 = g_x2sum + (size_t)r1 * 16;
            red_add_v4(d1,      mb[0],  mb[1],  mb[2],  mb[3]);
            red_add_v4(d1 + 4,  mb[4],  mb[5],  mb[6],  mb[7]);
            red_add_v4(d1 + 8,  mb[8],  mb[9],  mb[10], mb[11]);
            red_add_v4(d1 + 12, mb[12], mb[13], mb[14], mb[15]);
        }
    }
}

// -------------------- node finalize + graph scatter --------------------
__global__ void node_kernel(const int* __restrict__ batch, int N)
{
    int n = blockIdx.x * blockDim.x + threadIdx.x;
    if (n >= N) return;
    const float* sp = g_x2sum + (size_t)n * 16;
    float inv = 1.f / fmaxf(sp[15], 1.f);
    float v[16];
    #pragma unroll
    for (int j = 0; j < D3; j++) v[j] = sp[j] * inv;
    v[15] = 1.0f;
    float* dst = g_gsum + (size_t)batch[n] * 16;
    red_add_v4(dst,      v[0],  v[1],  v[2],  v[3]);
    red_add_v4(dst + 4,  v[4],  v[5],  v[6],  v[7]);
    red_add_v4(dst + 8,  v[8],  v[9],  v[10], v[11]);
    red_add_v4(dst + 12, v[12], v[13], v[14], v[15]);
}

// -------------------- global MLP + fc1 + BN stats (warp per graph) -------
__global__ __launch_bounds__(256)
void global_kernel(const float* __restrict__ u,
                   const float* __restrict__ gw1, const float* __restrict__ gb1,
                   const float* __restrict__ gw2, const float* __restrict__ gb2,
                   const float* __restrict__ f1w, const float* __restrict__ f1b,
                   int G)
{
    __shared__ float sh[8][52];
    __shared__ float su[8][16];
    int w = threadIdx.x >> 5;
    int lane = threadIdx.x & 31;
    int gi = blockIdx.x * 8 + w;
    if (gi >= G) return;

    float gin[16];
    gin[0] = u[gi];
    const float* sp = g_gsum + (size_t)gi * 16;
    float inv = 1.f / fmaxf(__ldg(&sp[15]), 1.f);
    #pragma unroll
    for (int j = 0; j < D3; j++) gin[1 + j] = __ldg(&sp[j]) * inv;

    {
        int j = lane;
        float a = gb1[j];
        #pragma unroll
        for (int k = 0; k < 16; k++) a += gin[k] * gw1[k * H + j];
        sh[w][j] = fmaxf(a, 0.f);
        if (lane < H - 32) {
            int j2 = lane + 32;
            float a2 = gb1[j2];
            #pragma unroll
            for (int k = 0; k < 16; k++) a2 += gin[k] * gw1[k * H + j2];
            sh[w][j2] = fmaxf(a2, 0.f);
        }
    }
    __syncwarp();
    if (lane < D3) {
        float a = gb2[lane];
        #pragma unroll
        for (int k = 0; k < H; k++) a += sh[w][k] * gw2[k * D3 + lane];
        su[w][lane] = a;
    }
    __syncwarp();
    if (lane < D5) {
        float a = f1b[lane];
        #pragma unroll
        for (int k = 0; k < D3; k++) a += su[w][k] * f1w[k * D5 + lane];
        g_z[gi * D5 + lane] = a;
        atomicAdd(&g_zstat[lane], a);
        atomicAdd(&g_zstat[D5 + lane], a * a);
    }
}

// -------------------- BN + ReLU + fc2 + log_softmax --------------------
__global__ void head_kernel(const float* __restrict__ bn_g, const float* __restrict__ bn_b,
                            const float* __restrict__ f2w, const float* __restrict__ f2b,
                            float* __restrict__ out, int G)
{
    int gi = blockIdx.x * blockDim.x + threadIdx.x;
    if (gi >= G) return;
    float invG = 1.f / (float)G;
    float zr[D5];
    #pragma unroll
    for (int j = 0; j < D5; j++) {
        float mean = g_zstat[j] * invG;
        float var  = g_zstat[D5 + j] * invG - mean * mean;
        float zn = (g_z[gi * D5 + j] - mean) * rsqrtf(var + EPS) * bn_g[j] + bn_b[j];
        zr[j] = fmaxf(zn, 0.f);
    }
    float lg[NC];
    float mx = -1e30f;
    #pragma unroll
    for (int j = 0; j < NC; j++) {
        float a = f2b[j];
        #pragma unroll
        for (int k = 0; k < D5; k++) a += zr[k] * f2w[k * NC + j];
        lg[j] = a;
        mx = fmaxf(mx, a);
    }
    float se = 0.f;
    #pragma unroll
    for (int j = 0; j < NC; j++) se += expf(lg[j] - mx);
    float lse = mx + logf(se);
    #pragma unroll
    for (int j = 0; j < NC; j++) out[gi * NC + j] = lg[j] - lse;
}

// -------------------- launch --------------------
extern "C" void kernel_launch(void* const* d_in, const int* in_sizes, int n_in,
                              void* d_out, int out_size)
{
    const float* x     = (const float*)d_in[0];
    const int*   ei    = (const int*)  d_in[1];
    const float* ea    = (const float*)d_in[2];
    const float* u     = (const float*)d_in[3];
    const int*   batch = (const int*)  d_in[4];
    const float* ew1 = (const float*)d_in[5];
    const float* eb1 = (const float*)d_in[6];
    const float* ew2 = (const float*)d_in[7];
    const float* eb2 = (const float*)d_in[8];
    const float* nw1 = (const float*)d_in[9];
    const float* nb1 = (const float*)d_in[10];
    const float* nw2 = (const float*)d_in[11];
    const float* nb2 = (const float*)d_in[12];
    const float* gw1 = (const float*)d_in[13];
    const float* gb1 = (const float*)d_in[14];
    const float* gw2 = (const float*)d_in[15];
    const float* gb2 = (const float*)d_in[16];
    const float* f1w = (const float*)d_in[17];
    const float* f1b = (const float*)d_in[18];
    const float* bn_g = (const float*)d_in[19];
    const float* bn_b = (const float*)d_in[20];
    const float* f2w = (const float*)d_in[21];
    const float* f2b = (const float*)d_in[22];
    float* out = (float*)d_out;

    int N = in_sizes[0] / 3;
    int E = in_sizes[1] / 2;
    int G = in_sizes[3];

    {
        int n_x2 = N * 16, n_g = G * 16;
        int blocks = (n_x2 + TPB - 1) / TPB;
        if (blocks > 4096) blocks = 4096;
        zero_kernel<<<blocks, TPB>>>(n_x2, n_g);
    }
    {
        int npairs = (E + 1) / 2;
        int blocks = 152 * 4;
        int need = (npairs + TPB - 1) / TPB;
        if (need < blocks) blocks = need;
        edge_kernel<<<blocks, TPB>>>(x, ei, ea, ew1, eb1, ew2, eb2,
                                     nw1, nb1, nw2, nb2, E);
    }
    node_kernel<<<(N + TPB - 1) / TPB, TPB>>>(batch, N);
    global_kernel<<<(G + 7) / 8, 256>>>(u, gw1, gb1, gw2, gb2, f1w, f1b, G);
    head_kernel<<<(G + TPB - 1) / TPB, TPB>>>(bn_g, bn_b, f2w, f2b, out, G);
}

// round 5
// speedup vs baseline: 1.5610x; 1.5610x over previous
#include <cuda_runtime.h>
#include <math.h>

#define MAXN 100000
#define MAXG 1000
#define H  50
#define D3 15
#define D5 10
#define NC 6
#define EPS 1e-5f
#define TPB 256

// -------- scratch (device globals) --------
__device__ float g_x2sum[MAXN * 16];
__device__ float g_gsum[MAXG * 16];
__device__ float g_z[MAXG * D5];
__device__ float g_zstat[2 * D5];

// -------- helpers --------
__device__ __forceinline__ unsigned f2tf(float f) {
    unsigned r; asm("cvt.rna.tf32.f32 %0, %1;" : "=r"(r) : "f"(f)); return r;
}
__device__ __forceinline__ void mma8(float c[4], const unsigned a[4], unsigned b0, unsigned b1) {
    asm volatile("mma.sync.aligned.m16n8k8.row.col.f32.tf32.tf32.f32 "
        "{%0,%1,%2,%3}, {%4,%5,%6,%7}, {%8,%9}, {%0,%1,%2,%3};"
        : "+f"(c[0]), "+f"(c[1]), "+f"(c[2]), "+f"(c[3])
        : "r"(a[0]), "r"(a[1]), "r"(a[2]), "r"(a[3]), "r"(b0), "r"(b1));
}
__device__ __forceinline__ void red2(float* p, float a, float b) {
    asm volatile("red.global.add.v2.f32 [%0], {%1,%2};" :: "l"(p), "f"(a), "f"(b) : "memory");
}
__device__ __forceinline__ void red_add_v4(float* dst, float a, float b, float c, float d) {
    asm volatile("red.global.add.v4.f32 [%0], {%1,%2,%3,%4};"
                 :: "l"(dst), "f"(a), "f"(b), "f"(c), "f"(d) : "memory");
}

// -------------------- zero scratch --------------------
__global__ void zero_kernel(int n_x2, int n_g) {
    int i = blockIdx.x * blockDim.x + threadIdx.x;
    int stride = gridDim.x * blockDim.x;
    for (int k = i; k < n_x2; k += stride) g_x2sum[k] = 0.f;
    for (int k = i; k < n_g;  k += stride) g_gsum[k]  = 0.f;
    if (i < 2 * D5) g_zstat[i] = 0.f;
}

// SMEM layout (float/unsigned units)
#define O_W1EH 0        // [16k][56n]
#define O_W1EL 896
#define O_W2EH 1792     // [56k][24n] (15 used)
#define O_W2EL 3136
#define O_W1NH 4480     // [24k][56n]
#define O_W1NL 5824
#define O_W2NH 7168     // [56k][24n]
#define O_W2NL 8512
#define O_B1E  9856     // 56
#define O_B2E  9912     // 16
#define O_B1N  9928     // 56
#define O_B2N  9984     // 16
#define O_ACT  10000
#define ACT_PER_WARP 2816   // actA [32][28] + actH [32][60]
#define SMEM_FLOATS (O_ACT + 8 * ACT_PER_WARP)
#define SMEM_BYTES  (SMEM_FLOATS * 4)

// GEMM: D[32, NT*8] = A[32, KT*8] @ (Bhi+Blo), bias-init C.
template<int KT, int NT, int SA, int SB>
__device__ __forceinline__ void gemm_split(const float* sA,
                                           const unsigned* sBh, const unsigned* sBl,
                                           const float* bias, float (*C)[4],
                                           int qid, int tq)
{
    #pragma unroll
    for (int nt = 0; nt < NT; nt++) {
        float bx = bias[nt * 8 + 2 * tq];
        float by = bias[nt * 8 + 2 * tq + 1];
        #pragma unroll
        for (int mt = 0; mt < 2; mt++) {
            C[mt * NT + nt][0] = bx; C[mt * NT + nt][1] = by;
            C[mt * NT + nt][2] = bx; C[mt * NT + nt][3] = by;
        }
    }
    #pragma unroll
    for (int kt = 0; kt < KT; kt++) {
        unsigned a[2][4];
        #pragma unroll
        for (int mt = 0; mt < 2; mt++) {
            const float* p = sA + (mt * 16 + qid) * SA + kt * 8 + tq;
            a[mt][0] = f2tf(p[0]);
            a[mt][1] = f2tf(p[8 * SA]);
            a[mt][2] = f2tf(p[4]);
            a[mt][3] = f2tf(p[8 * SA + 4]);
        }
        #pragma unroll
        for (int nt = 0; nt < NT; nt++) {
            int bi = (kt * 8 + tq) * SB + nt * 8 + qid;
            unsigned b0h = sBh[bi], b1h = sBh[bi + 4 * SB];
            unsigned b0l = sBl[bi], b1l = sBl[bi + 4 * SB];
            mma8(C[0 * NT + nt], a[0], b0h, b1h);
            mma8(C[1 * NT + nt], a[1], b0h, b1h);
            mma8(C[0 * NT + nt], a[0], b0l, b1l);
            mma8(C[1 * NT + nt], a[1], b0l, b1l);
        }
    }
}

// -------------------- edge pipeline (tensor cores) --------------------
__global__ __launch_bounds__(TPB)
void edge_mma_kernel(const float* __restrict__ x, const int* __restrict__ ei,
                     const float* __restrict__ ea,
                     const float* __restrict__ ew1, const float* __restrict__ eb1,
                     const float* __restrict__ ew2, const float* __restrict__ eb2,
                     const float* __restrict__ nw1, const float* __restrict__ nb1,
                     const float* __restrict__ nw2, const float* __restrict__ nb2,
                     int E, int ntiles)
{
    extern __shared__ float sm[];
    unsigned* um = reinterpret_cast<unsigned*>(sm);
    int tid = threadIdx.x;

    // ---- preamble: pad + transpose-free weight staging, hi/lo tf32 split ----
    for (int i = tid; i < 16 * 56; i += TPB) {            // eW1 [9->16 k][50->56 n]
        int k = i / 56, n = i % 56;
        float w = (k < 9 && n < 50) ? ew1[k * 50 + n] : 0.f;
        unsigned hi = f2tf(w);
        um[O_W1EH + i] = hi;
        um[O_W1EL + i] = f2tf(w - __uint_as_float(hi));
    }
    for (int i = tid; i < 56 * 24; i += TPB) {            // eW2 [50->56 k][15->24 n]
        int k = i / 24, n = i % 24;
        float w = (k < 50 && n < 15) ? ew2[k * 15 + n] : 0.f;
        unsigned hi = f2tf(w);
        um[O_W2EH + i] = hi;
        um[O_W2EL + i] = f2tf(w - __uint_as_float(hi));
    }
    for (int i = tid; i < 24 * 56; i += TPB) {            // nW1 [18->24 k][50->56 n]
        int k = i / 56, n = i % 56;
        float w = (k < 18 && n < 50) ? nw1[k * 50 + n] : 0.f;
        unsigned hi = f2tf(w);
        um[O_W1NH + i] = hi;
        um[O_W1NL + i] = f2tf(w - __uint_as_float(hi));
    }
    for (int i = tid; i < 56 * 24; i += TPB) {            // nW2 [50->56 k][15->24 n]
        int k = i / 24, n = i % 24;
        float w = (k < 50 && n < 15) ? nw2[k * 15 + n] : 0.f;
        unsigned hi = f2tf(w);
        um[O_W2NH + i] = hi;
        um[O_W2NL + i] = f2tf(w - __uint_as_float(hi));
    }
    for (int i = tid; i < 56; i += TPB) sm[O_B1E + i] = (i < 50) ? eb1[i] : 0.f;
    for (int i = tid; i < 16; i += TPB) sm[O_B2E + i] = (i < 15) ? eb2[i] : 0.f;
    for (int i = tid; i < 56; i += TPB) sm[O_B1N + i] = (i < 50) ? nb1[i] : 0.f;
    for (int i = tid; i < 16; i += TPB) sm[O_B2N + i] = (i < 15) ? nb2[i] : 0.f;
    __syncthreads();

    int wid = tid >> 5, lane = tid & 31;
    int qid = lane >> 2, tq = lane & 3;
    float* actA = sm + O_ACT + wid * ACT_PER_WARP;   // [32][28]
    float* actH = actA + 32 * 28;                    // [32][60]

    // zero pad cols of actA (k 18..27 for nin; col 18 rewritten per-iter)
    #pragma unroll
    for (int j = 19; j < 28; j++) actA[lane * 28 + j] = 0.f;
    __syncwarp();

    const unsigned* uW1EH = um + O_W1EH; const unsigned* uW1EL = um + O_W1EL;
    const unsigned* uW2EH = um + O_W2EH; const unsigned* uW2EL = um + O_W2EL;
    const unsigned* uW1NH = um + O_W1NH; const unsigned* uW1NL = um + O_W1NL;
    const unsigned* uW2NH = um + O_W2NH; const unsigned* uW2NL = um + O_W2NL;

    for (int t = blockIdx.x; t < ntiles; t += gridDim.x) {
        int wbase = t * 256 + wid * 32;
        int e = wbase + lane;
        int el = (e < E) ? e : (E - 1);
        int r = ei[el];
        int c = ei[E + el];
        float xc0 = __ldg(&x[3 * c]), xc1 = __ldg(&x[3 * c + 1]), xc2 = __ldg(&x[3 * c + 2]);
        {
            float* A = actA + lane * 28;
            A[0] = __ldg(&x[3 * r]); A[1] = __ldg(&x[3 * r + 1]); A[2] = __ldg(&x[3 * r + 2]);
            A[3] = xc0; A[4] = xc1; A[5] = xc2;
            A[6] = ea[3 * el]; A[7] = ea[3 * el + 1]; A[8] = ea[3 * el + 2];
            #pragma unroll
            for (int j = 9; j < 16; j++) A[j] = 0.f;
        }
        __syncwarp();

        // ---- L1: in0[32,16] @ eW1 -> h[32,56], relu -> actH ----
        {
            float C1[14][4];
            gemm_split<2, 7, 28, 56>(actA, uW1EH, uW1EL, sm + O_B1E, C1, qid, tq);
            #pragma unroll
            for (int mt = 0; mt < 2; mt++)
                #pragma unroll
                for (int nt = 0; nt < 7; nt++) {
                    float* cc = C1[mt * 7 + nt];
                    int r0 = mt * 16 + qid;
                    int col = nt * 8 + 2 * tq;
                    float2 v0 = make_float2(fmaxf(cc[0], 0.f), fmaxf(cc[1], 0.f));
                    float2 v1 = make_float2(fmaxf(cc[2], 0.f), fmaxf(cc[3], 0.f));
                    *reinterpret_cast<float2*>(actH + r0 * 60 + col) = v0;
                    *reinterpret_cast<float2*>(actH + (r0 + 8) * 60 + col) = v1;
                }
        }
        __syncwarp();

        // ---- L2: h[32,56] @ eW2 -> e2[32,16]; build nin in actA ----
        {
            float C2[4][4];
            gemm_split<7, 2, 60, 24>(actH, uW2EH, uW2EL, sm + O_B2E, C2, qid, tq);
            float* A = actA + lane * 28;
            A[0] = xc0; A[1] = xc1; A[2] = xc2;
            #pragma unroll
            for (int mt = 0; mt < 2; mt++)
                #pragma unroll
                for (int nt = 0; nt < 2; nt++) {
                    float* cc = C2[mt * 2 + nt];
                    int r0 = mt * 16 + qid;
                    int col = 3 + nt * 8 + 2 * tq;
                    actA[r0 * 28 + col]       = cc[0];
                    actA[r0 * 28 + col + 1]   = cc[1];
                    actA[(r0 + 8) * 28 + col]     = cc[2];
                    actA[(r0 + 8) * 28 + col + 1] = cc[3];
                }
        }
        __syncwarp();

        // ---- L3: nin[32,24] @ nW1 -> g[32,56], relu -> actH ----
        {
            float C3[14][4];
            gemm_split<3, 7, 28, 56>(actA, uW1NH, uW1NL, sm + O_B1N, C3, qid, tq);
            #pragma unroll
            for (int mt = 0; mt < 2; mt++)
                #pragma unroll
                for (int nt = 0; nt < 7; nt++) {
                    float* cc = C3[mt * 7 + nt];
                    int r0 = mt * 16 + qid;
                    int col = nt * 8 + 2 * tq;
                    float2 v0 = make_float2(fmaxf(cc[0], 0.f), fmaxf(cc[1], 0.f));
                    float2 v1 = make_float2(fmaxf(cc[2], 0.f), fmaxf(cc[3], 0.f));
                    *reinterpret_cast<float2*>(actH + r0 * 60 + col) = v0;
                    *reinterpret_cast<float2*>(actH + (r0 + 8) * 60 + col) = v1;
                }
        }
        __syncwarp();

        // ---- L4: g[32,56] @ nW2 -> m[32,16]; scatter-add by row node ----
        {
            float C4[4][4];
            gemm_split<7, 2, 60, 24>(actH, uW2NH, uW2NL, sm + O_B2N, C4, qid, tq);
            #pragma unroll
            for (int mt = 0; mt < 2; mt++)
                #pragma unroll
                for (int rr = 0; rr < 2; rr++) {
                    int row = mt * 16 + rr * 8 + qid;
                    int rnode = __shfl_sync(0xffffffffu, r, row);
                    if (wbase + row < E) {
                        float* dst = g_x2sum + (size_t)rnode * 16;
                        float* c0 = C4[mt * 2 + 0];
                        float* c1 = C4[mt * 2 + 1];
                        red2(dst + 2 * tq, c0[rr * 2 + 0], c0[rr * 2 + 1]);
                        float v1 = (tq == 3) ? 1.0f : c1[rr * 2 + 1];
                        red2(dst + 8 + 2 * tq, c1[rr * 2 + 0], v1);
                    }
                }
        }
        __syncwarp();
    }
}

// -------------------- node finalize + graph scatter --------------------
__global__ void node_kernel(const int* __restrict__ batch, int N)
{
    int n = blockIdx.x * blockDim.x + threadIdx.x;
    if (n >= N) return;
    const float* sp = g_x2sum + (size_t)n * 16;
    float inv = 1.f / fmaxf(sp[15], 1.f);
    float v[16];
    #pragma unroll
    for (int j = 0; j < D3; j++) v[j] = sp[j] * inv;
    v[15] = 1.0f;
    float* dst = g_gsum + (size_t)batch[n] * 16;
    red_add_v4(dst,      v[0],  v[1],  v[2],  v[3]);
    red_add_v4(dst + 4,  v[4],  v[5],  v[6],  v[7]);
    red_add_v4(dst + 8,  v[8],  v[9],  v[10], v[11]);
    red_add_v4(dst + 12, v[12], v[13], v[14], v[15]);
}

// -------------------- global MLP + fc1 + BN stats (warp per graph) -------
__global__ __launch_bounds__(256)
void global_kernel(const float* __restrict__ u,
                   const float* __restrict__ gw1, const float* __restrict__ gb1,
                   const float* __restrict__ gw2, const float* __restrict__ gb2,
                   const float* __restrict__ f1w, const float* __restrict__ f1b,
                   int G)
{
    __shared__ float sh[8][52];
    __shared__ float su[8][16];
    int w = threadIdx.x >> 5;
    int lane = threadIdx.x & 31;
    int gi = blockIdx.x * 8 + w;
    if (gi >= G) return;

    float gin[16];
    gin[0] = u[gi];
    const float* sp = g_gsum + (size_t)gi * 16;
    float inv = 1.f / fmaxf(__ldg(&sp[15]), 1.f);
    #pragma unroll
    for (int j = 0; j < D3; j++) gin[1 + j] = __ldg(&sp[j]) * inv;

    {
        int j = lane;
        float a = gb1[j];
        #pragma unroll
        for (int k = 0; k < 16; k++) a += gin[k] * gw1[k * H + j];
        sh[w][j] = fmaxf(a, 0.f);
        if (lane < H - 32) {
            int j2 = lane + 32;
            float a2 = gb1[j2];
            #pragma unroll
            for (int k = 0; k < 16; k++) a2 += gin[k] * gw1[k * H + j2];
            sh[w][j2] = fmaxf(a2, 0.f);
        }
    }
    __syncwarp();
    if (lane < D3) {
        float a = gb2[lane];
        #pragma unroll
        for (int k = 0; k < H; k++) a += sh[w][k] * gw2[k * D3 + lane];
        su[w][lane] = a;
    }
    __syncwarp();
    if (lane < D5) {
        float a = f1b[lane];
        #pragma unroll
        for (int k = 0; k < D3; k++) a += su[w][k] * f1w[k * D5 + lane];
        g_z[gi * D5 + lane] = a;
        atomicAdd(&g_zstat[lane], a);
        atomicAdd(&g_zstat[D5 + lane], a * a);
    }
}

// -------------------- BN + ReLU + fc2 + log_softmax --------------------
__global__ void head_kernel(const float* __restrict__ bn_g, const float* __restrict__ bn_b,
                            const float* __restrict__ f2w, const float* __restrict__ f2b,
                            float* __restrict__ out, int G)
{
    int gi = blockIdx.x * blockDim.x + threadIdx.x;
    if (gi >= G) return;
    float invG = 1.f / (float)G;
    float zr[D5];
    #pragma unroll
    for (int j = 0; j < D5; j++) {
        float mean = g_zstat[j] * invG;
        float var  = g_zstat[D5 + j] * invG - mean * mean;
        float zn = (g_z[gi * D5 + j] - mean) * rsqrtf(var + EPS) * bn_g[j] + bn_b[j];
        zr[j] = fmaxf(zn, 0.f);
    }
    float lg[NC];
    float mx = -1e30f;
    #pragma unroll
    for (int j = 0; j < NC; j++) {
        float a = f2b[j];
        #pragma unroll
        for (int k = 0; k < D5; k++) a += zr[k] * f2w[k * NC + j];
        lg[j] = a;
        mx = fmaxf(mx, a);
    }
    float se = 0.f;
    #pragma unroll
    for (int j = 0; j < NC; j++) se += expf(lg[j] - mx);
    float lse = mx + logf(se);
    #pragma unroll
    for (int j = 0; j < NC; j++) out[gi * NC + j] = lg[j] - lse;
}

// -------------------- launch --------------------
extern "C" void kernel_launch(void* const* d_in, const int* in_sizes, int n_in,
                              void* d_out, int out_size)
{
    const float* x     = (const float*)d_in[0];
    const int*   ei    = (const int*)  d_in[1];
    const float* ea    = (const float*)d_in[2];
    const float* u     = (const float*)d_in[3];
    const int*   batch = (const int*)  d_in[4];
    const float* ew1 = (const float*)d_in[5];
    const float* eb1 = (const float*)d_in[6];
    const float* ew2 = (const float*)d_in[7];
    const float* eb2 = (const float*)d_in[8];
    const float* nw1 = (const float*)d_in[9];
    const float* nb1 = (const float*)d_in[10];
    const float* nw2 = (const float*)d_in[11];
    const float* nb2 = (const float*)d_in[12];
    const float* gw1 = (const float*)d_in[13];
    const float* gb1 = (const float*)d_in[14];
    const float* gw2 = (const float*)d_in[15];
    const float* gb2 = (const float*)d_in[16];
    const float* f1w = (const float*)d_in[17];
    const float* f1b = (const float*)d_in[18];
    const float* bn_g = (const float*)d_in[19];
    const float* bn_b = (const float*)d_in[20];
    const float* f2w = (const float*)d_in[21];
    const float* f2b = (const float*)d_in[22];
    float* out = (float*)d_out;

    int N = in_sizes[0] / 3;
    int E = in_sizes[1] / 2;
    int G = in_sizes[3];

    {
        int n_x2 = N * 16, n_g = G * 16;
        int blocks = (n_x2 + TPB - 1) / TPB;
        if (blocks > 4096) blocks = 4096;
        zero_kernel<<<blocks, TPB>>>(n_x2, n_g);
    }
    {
        cudaFuncSetAttribute(edge_mma_kernel,
                             cudaFuncAttributeMaxDynamicSharedMemorySize, SMEM_BYTES);
        int ntiles = (E + 255) / 256;
        int blocks = 148;
        if (ntiles < blocks) blocks = ntiles;
        edge_mma_kernel<<<blocks, TPB, SMEM_BYTES>>>(x, ei, ea, ew1, eb1, ew2, eb2,
                                                     nw1, nb1, nw2, nb2, E, ntiles);
    }
    node_kernel<<<(N + TPB - 1) / TPB, TPB>>>(batch, N);
    global_kernel<<<(G + 7) / 8, 256>>>(u, gw1, gb1, gw2, gb2, f1w, f1b, G);
    head_kernel<<<(G + TPB - 1) / TPB, TPB>>>(bn_g, bn_b, f2w, f2b, out, G);
}

// round 7
// speedup vs baseline: 1.8865x; 1.2085x over previous
#include <cuda_runtime.h>
#include <math.h>

#define MAXN 100000
#define MAXG 1000
#define H  50
#define D3 15
#define D5 10
#define NC 6
#define EPS 1e-5f
#define TPB 256

// -------- scratch (device globals) --------
__device__ float g_x2sum[MAXN * 16];
__device__ float g_gsum[MAXG * 16];
__device__ float g_z[MAXG * D5];
__device__ float g_zstat[2 * D5];

// -------- helpers --------
__device__ __forceinline__ unsigned f2tf(float f) {
    unsigned r; asm("cvt.rna.tf32.f32 %0, %1;" : "=r"(r) : "f"(f)); return r;
}
__device__ __forceinline__ void mma8(float c[4], const unsigned a[4], unsigned b0, unsigned b1) {
    asm volatile("mma.sync.aligned.m16n8k8.row.col.f32.tf32.tf32.f32 "
        "{%0,%1,%2,%3}, {%4,%5,%6,%7}, {%8,%9}, {%0,%1,%2,%3};"
        : "+f"(c[0]), "+f"(c[1]), "+f"(c[2]), "+f"(c[3])
        : "r"(a[0]), "r"(a[1]), "r"(a[2]), "r"(a[3]), "r"(b0), "r"(b1));
}
__device__ __forceinline__ void red2(float* p, float a, float b) {
    asm volatile("red.global.add.v2.f32 [%0], {%1,%2};" :: "l"(p), "f"(a), "f"(b) : "memory");
}
__device__ __forceinline__ void red_add_v4(float* dst, float a, float b, float c, float d) {
    asm volatile("red.global.add.v4.f32 [%0], {%1,%2,%3,%4};"
                 :: "l"(dst), "f"(a), "f"(b), "f"(c), "f"(d) : "memory");
}

// -------------------- zero scratch --------------------
__global__ void zero_kernel(int n_x2, int n_g) {
    int i = blockIdx.x * blockDim.x + threadIdx.x;
    int stride = gridDim.x * blockDim.x;
    for (int k = i; k < n_x2; k += stride) g_x2sum[k] = 0.f;
    for (int k = i; k < n_g;  k += stride) g_gsum[k]  = 0.f;
    if (i < 2 * D5) g_zstat[i] = 0.f;
}

// SMEM layout (float/unsigned units) — single tf32 weights
#define O_W1E  0        // [16k][56n]  896
#define O_W2E  896      // [56k][24n]  1344
#define O_W1N  2240     // [24k][56n]  1344
#define O_W2N  3584     // [56k][24n]  1344
#define O_B1E  4928     // 56
#define O_B2E  4984     // 16
#define O_B1N  5000     // 56
#define O_B2N  5056     // 16
#define O_ACT  5072
#define ACT_PER_WARP 2816   // actA [32][28] + actH [32][60]
#define SMEM_FLOATS (O_ACT + 8 * ACT_PER_WARP)
#define SMEM_BYTES  (SMEM_FLOATS * 4)

// GEMM: D[32, NT*8] = A[32, KT*8] @ B(tf32), bias-init C.
template<int KT, int NT, int SA, int SB>
__device__ __forceinline__ void gemm(const float* sA, const unsigned* sB,
                                     const float* bias, float (*C)[4],
                                     int qid, int tq)
{
    #pragma unroll
    for (int nt = 0; nt < NT; nt++) {
        float bx = bias[nt * 8 + 2 * tq];
        float by = bias[nt * 8 + 2 * tq + 1];
        #pragma unroll
        for (int mt = 0; mt < 2; mt++) {
            C[mt * NT + nt][0] = bx; C[mt * NT + nt][1] = by;
            C[mt * NT + nt][2] = bx; C[mt * NT + nt][3] = by;
        }
    }
    #pragma unroll
    for (int kt = 0; kt < KT; kt++) {
        unsigned a[2][4];
        #pragma unroll
        for (int mt = 0; mt < 2; mt++) {
            const float* p = sA + (mt * 16 + qid) * SA + kt * 8 + tq;
            a[mt][0] = f2tf(p[0]);
            a[mt][1] = f2tf(p[8 * SA]);
            a[mt][2] = f2tf(p[4]);
            a[mt][3] = f2tf(p[8 * SA + 4]);
        }
        #pragma unroll
        for (int nt = 0; nt < NT; nt++) {
            int bi = (kt * 8 + tq) * SB + nt * 8 + qid;
            unsigned b0 = sB[bi], b1 = sB[bi + 4 * SB];
            mma8(C[0 * NT + nt], a[0], b0, b1);
            mma8(C[1 * NT + nt], a[1], b0, b1);
        }
    }
}

// -------------------- edge pipeline (tensor cores) --------------------
__global__ __launch_bounds__(TPB, 2)
void edge_mma_kernel(const float* __restrict__ x, const int* __restrict__ ei,
                     const float* __restrict__ ea,
                     const float* __restrict__ ew1, const float* __restrict__ eb1,
                     const float* __restrict__ ew2, const float* __restrict__ eb2,
                     const float* __restrict__ nw1, const float* __restrict__ nb1,
                     const float* __restrict__ nw2, const float* __restrict__ nb2,
                     int E, int ntiles)
{
    extern __shared__ float sm[];
    unsigned* um = reinterpret_cast<unsigned*>(sm);
    int tid = threadIdx.x;

    // ---- preamble: pad weights to MMA tiles, tf32 convert ----
    for (int i = tid; i < 16 * 56; i += TPB) {            // eW1 [9->16 k][50->56 n]
        int k = i / 56, n = i % 56;
        float w = (k < 9 && n < 50) ? ew1[k * 50 + n] : 0.f;
        um[O_W1E + i] = f2tf(w);
    }
    for (int i = tid; i < 56 * 24; i += TPB) {            // eW2 [50->56 k][15->24 n]
        int k = i / 24, n = i % 24;
        float w = (k < 50 && n < 15) ? ew2[k * 15 + n] : 0.f;
        um[O_W2E + i] = f2tf(w);
    }
    for (int i = tid; i < 24 * 56; i += TPB) {            // nW1 [18->24 k][50->56 n]
        int k = i / 56, n = i % 56;
        float w = (k < 18 && n < 50) ? nw1[k * 50 + n] : 0.f;
        um[O_W1N + i] = f2tf(w);
    }
    for (int i = tid; i < 56 * 24; i += TPB) {            // nW2 [50->56 k][15->24 n]
        int k = i / 24, n = i % 24;
        float w = (k < 50 && n < 15) ? nw2[k * 15 + n] : 0.f;
        um[O_W2N + i] = f2tf(w);
    }
    for (int i = tid; i < 56; i += TPB) sm[O_B1E + i] = (i < 50) ? eb1[i] : 0.f;
    for (int i = tid; i < 16; i += TPB) sm[O_B2E + i] = (i < 15) ? eb2[i] : 0.f;
    for (int i = tid; i < 56; i += TPB) sm[O_B1N + i] = (i < 50) ? nb1[i] : 0.f;
    for (int i = tid; i < 16; i += TPB) sm[O_B2N + i] = (i < 15) ? nb2[i] : 0.f;
    __syncthreads();

    int wid = tid >> 5, lane = tid & 31;
    int qid = lane >> 2, tq = lane & 3;
    float* actA = sm + O_ACT + wid * ACT_PER_WARP;   // [32][28]
    float* actH = actA + 32 * 28;                    // [32][60]

    // zero pad cols of actA (k 19..27; col 18 rewritten per-iter)
    #pragma unroll
    for (int j = 19; j < 28; j++) actA[lane * 28 + j] = 0.f;
    __syncwarp();

    const unsigned* uW1E = um + O_W1E;
    const unsigned* uW2E = um + O_W2E;
    const unsigned* uW1N = um + O_W1N;
    const unsigned* uW2N = um + O_W2N;

    for (int t = blockIdx.x; t < ntiles; t += gridDim.x) {
        int wbase = t * 256 + wid * 32;
        int e = wbase + lane;
        int el = (e < E) ? e : (E - 1);
        int r = ei[el];
        int c = ei[E + el];
        float xc0 = __ldg(&x[3 * c]), xc1 = __ldg(&x[3 * c + 1]), xc2 = __ldg(&x[3 * c + 2]);
        {
            float* A = actA + lane * 28;
            A[0] = __ldg(&x[3 * r]); A[1] = __ldg(&x[3 * r + 1]); A[2] = __ldg(&x[3 * r + 2]);
            A[3] = xc0; A[4] = xc1; A[5] = xc2;
            A[6] = ea[3 * el]; A[7] = ea[3 * el + 1]; A[8] = ea[3 * el + 2];
            #pragma unroll
            for (int j = 9; j < 16; j++) A[j] = 0.f;
        }
        __syncwarp();

        // ---- L1: in0[32,16] @ eW1 -> h[32,56], relu -> actH ----
        {
            float C1[14][4];
            gemm<2, 7, 28, 56>(actA, uW1E, sm + O_B1E, C1, qid, tq);
            #pragma unroll
            for (int mt = 0; mt < 2; mt++)
                #pragma unroll
                for (int nt = 0; nt < 7; nt++) {
                    float* cc = C1[mt * 7 + nt];
                    int r0 = mt * 16 + qid;
                    int col = nt * 8 + 2 * tq;
                    float2 v0 = make_float2(fmaxf(cc[0], 0.f), fmaxf(cc[1], 0.f));
                    float2 v1 = make_float2(fmaxf(cc[2], 0.f), fmaxf(cc[3], 0.f));
                    *reinterpret_cast<float2*>(actH + r0 * 60 + col) = v0;
                    *reinterpret_cast<float2*>(actH + (r0 + 8) * 60 + col) = v1;
                }
        }
        __syncwarp();

        // ---- L2: h[32,56] @ eW2 -> e2[32,16]; build nin in actA ----
        {
            float C2[4][4];
            gemm<7, 2, 60, 24>(actH, uW2E, sm + O_B2E, C2, qid, tq);
            float* A = actA + lane * 28;
            A[0] = xc0; A[1] = xc1; A[2] = xc2;
            #pragma unroll
            for (int mt = 0; mt < 2; mt++)
                #pragma unroll
                for (int nt = 0; nt < 2; nt++) {
                    float* cc = C2[mt * 2 + nt];
                    int r0 = mt * 16 + qid;
                    int col = 3 + nt * 8 + 2 * tq;
                    actA[r0 * 28 + col]       = cc[0];
                    actA[r0 * 28 + col + 1]   = cc[1];
                    actA[(r0 + 8) * 28 + col]     = cc[2];
                    actA[(r0 + 8) * 28 + col + 1] = cc[3];
                }
        }
        __syncwarp();

        // ---- L3: nin[32,24] @ nW1 -> g[32,56], relu -> actH ----
        {
            float C3[14][4];
            gemm<3, 7, 28, 56>(actA, uW1N, sm + O_B1N, C3, qid, tq);
            #pragma unroll
            for (int mt = 0; mt < 2; mt++)
                #pragma unroll
                for (int nt = 0; nt < 7; nt++) {
                    float* cc = C3[mt * 7 + nt];
                    int r0 = mt * 16 + qid;
                    int col = nt * 8 + 2 * tq;
                    float2 v0 = make_float2(fmaxf(cc[0], 0.f), fmaxf(cc[1], 0.f));
                    float2 v1 = make_float2(fmaxf(cc[2], 0.f), fmaxf(cc[3], 0.f));
                    *reinterpret_cast<float2*>(actH + r0 * 60 + col) = v0;
                    *reinterpret_cast<float2*>(actH + (r0 + 8) * 60 + col) = v1;
                }
        }
        __syncwarp();

        // ---- L4: g[32,56] @ nW2 -> m[32,16]; scatter-add by row node ----
        {
            float C4[4][4];
            gemm<7, 2, 60, 24>(actH, uW2N, sm + O_B2N, C4, qid, tq);
            #pragma unroll
            for (int mt = 0; mt < 2; mt++)
                #pragma unroll
                for (int rr = 0; rr < 2; rr++) {
                    int row = mt * 16 + rr * 8 + qid;
                    int rnode = __shfl_sync(0xffffffffu, r, row);
                    if (wbase + row < E) {
                        float* dst = g_x2sum + (size_t)rnode * 16;
                        float* c0 = C4[mt * 2 + 0];
                        float* c1 = C4[mt * 2 + 1];
                        red2(dst + 2 * tq, c0[rr * 2 + 0], c0[rr * 2 + 1]);
                        float v1 = (tq == 3) ? 1.0f : c1[rr * 2 + 1];
                        red2(dst + 8 + 2 * tq, c1[rr * 2 + 0], v1);
                    }
                }
        }
        __syncwarp();
    }
}

// -------------------- node finalize + graph scatter --------------------
__global__ void node_kernel(const int* __restrict__ batch, int N)
{
    int n = blockIdx.x * blockDim.x + threadIdx.x;
    if (n >= N) return;
    const float* sp = g_x2sum + (size_t)n * 16;
    float inv = 1.f / fmaxf(sp[15], 1.f);
    float v[16];
    #pragma unroll
    for (int j = 0; j < D3; j++) v[j] = sp[j] * inv;
    v[15] = 1.0f;
    float* dst = g_gsum + (size_t)batch[n] * 16;
    red_add_v4(dst,      v[0],  v[1],  v[2],  v[3]);
    red_add_v4(dst + 4,  v[4],  v[5],  v[6],  v[7]);
    red_add_v4(dst + 8,  v[8],  v[9],  v[10], v[11]);
    red_add_v4(dst + 12, v[12], v[13], v[14], v[15]);
}

// -------------------- global MLP + fc1 + BN stats (warp per graph) -------
__global__ __launch_bounds__(256)
void global_kernel(const float* __restrict__ u,
                   const float* __restrict__ gw1, const float* __restrict__ gb1,
                   const float* __restrict__ gw2, const float* __restrict__ gb2,
                   const float* __restrict__ f1w, const float* __restrict__ f1b,
                   int G)
{
    __shared__ float sh[8][52];
    __shared__ float su[8][16];
    int w = threadIdx.x >> 5;
    int lane = threadIdx.x & 31;
    int gi = blockIdx.x * 8 + w;
    if (gi >= G) return;

    float gin[16];
    gin[0] = u[gi];
    const float* sp = g_gsum + (size_t)gi * 16;
    float inv = 1.f / fmaxf(__ldg(&sp[15]), 1.f);
    #pragma unroll
    for (int j = 0; j < D3; j++) gin[1 + j] = __ldg(&sp[j]) * inv;

    {
        int j = lane;
        float a = gb1[j];
        #pragma unroll
        for (int k = 0; k < 16; k++) a += gin[k] * gw1[k * H + j];
        sh[w][j] = fmaxf(a, 0.f);
        if (lane < H - 32) {
            int j2 = lane + 32;
            float a2 = gb1[j2];
            #pragma unroll
            for (int k = 0; k < 16; k++) a2 += gin[k] * gw1[k * H + j2];
            sh[w][j2] = fmaxf(a2, 0.f);
        }
    }
    __syncwarp();
    if (lane < D3) {
        float a = gb2[lane];
        #pragma unroll
        for (int k = 0; k < H; k++) a += sh[w][k] * gw2[k * D3 + lane];
        su[w][lane] = a;
    }
    __syncwarp();
    if (lane < D5) {
        float a = f1b[lane];
        #pragma unroll
        for (int k = 0; k < D3; k++) a += su[w][k] * f1w[k * D5 + lane];
        g_z[gi * D5 + lane] = a;
        atomicAdd(&g_zstat[lane], a);
        atomicAdd(&g_zstat[D5 + lane], a * a);
    }
}

// -------------------- BN + ReLU + fc2 + log_softmax --------------------
__global__ void head_kernel(const float* __restrict__ bn_g, const float* __restrict__ bn_b,
                            const float* __restrict__ f2w, const float* __restrict__ f2b,
                            float* __restrict__ out, int G)
{
    int gi = blockIdx.x * blockDim.x + threadIdx.x;
    if (gi >= G) return;
    float invG = 1.f / (float)G;
    float zr[D5];
    #pragma unroll
    for (int j = 0; j < D5; j++) {
        float mean = g_zstat[j] * invG;
        float var  = g_zstat[D5 + j] * invG - mean * mean;
        float zn = (g_z[gi * D5 + j] - mean) * rsqrtf(var + EPS) * bn_g[j] + bn_b[j];
        zr[j] = fmaxf(zn, 0.f);
    }
    float lg[NC];
    float mx = -1e30f;
    #pragma unroll
    for (int j = 0; j < NC; j++) {
        float a = f2b[j];
        #pragma unroll
        for (int k = 0; k < D5; k++) a += zr[k] * f2w[k * NC + j];
        lg[j] = a;
        mx = fmaxf(mx, a);
    }
    float se = 0.f;
    #pragma unroll
    for (int j = 0; j < NC; j++) se += expf(lg[j] - mx);
    float lse = mx + logf(se);
    #pragma unroll
    for (int j = 0; j < NC; j++) out[gi * NC + j] = lg[j] - lse;
}

// -------------------- launch --------------------
extern "C" void kernel_launch(void* const* d_in, const int* in_sizes, int n_in,
                              void* d_out, int out_size)
{
    const float* x     = (const float*)d_in[0];
    const int*   ei    = (const int*)  d_in[1];
    const float* ea    = (const float*)d_in[2];
    const float* u     = (const float*)d_in[3];
    const int*   batch = (const int*)  d_in[4];
    const float* ew1 = (const float*)d_in[5];
    const float* eb1 = (const float*)d_in[6];
    const float* ew2 = (const float*)d_in[7];
    const float* eb2 = (const float*)d_in[8];
    const float* nw1 = (const float*)d_in[9];
    const float* nb1 = (const float*)d_in[10];
    const float* nw2 = (const float*)d_in[11];
    const float* nb2 = (const float*)d_in[12];
    const float* gw1 = (const float*)d_in[13];
    const float* gb1 = (const float*)d_in[14];
    const float* gw2 = (const float*)d_in[15];
    const float* gb2 = (const float*)d_in[16];
    const float* f1w = (const float*)d_in[17];
    const float* f1b = (const float*)d_in[18];
    const float* bn_g = (const float*)d_in[19];
    const float* bn_b = (const float*)d_in[20];
    const float* f2w = (const float*)d_in[21];
    const float* f2b = (const float*)d_in[22];
    float* out = (float*)d_out;

    int N = in_sizes[0] / 3;
    int E = in_sizes[1] / 2;
    int G = in_sizes[3];

    {
        int n_x2 = N * 16, n_g = G * 16;
        int blocks = (n_x2 + TPB - 1) / TPB;
        if (blocks > 4096) blocks = 4096;
        zero_kernel<<<blocks, TPB>>>(n_x2, n_g);
    }
    {
        cudaFuncSetAttribute(edge_mma_kernel,
                             cudaFuncAttributeMaxDynamicSharedMemorySize, SMEM_BYTES);
        int ntiles = (E + 255) / 256;
        int blocks = 2 * 148;
        if (ntiles < blocks) blocks = ntiles;
        edge_mma_kernel<<<blocks, TPB, SMEM_BYTES>>>(x, ei, ea, ew1, eb1, ew2, eb2,
                                                     nw1, nb1, nw2, nb2, E, ntiles);
    }
    node_kernel<<<(N + TPB - 1) / TPB, TPB>>>(batch, N);
    global_kernel<<<(G + 7) / 8, 256>>>(u, gw1, gb1, gw2, gb2, f1w, f1b, G);
    head_kernel<<<(G + TPB - 1) / TPB, TPB>>>(bn_g, bn_b, f2w, f2b, out, G);
}

// round 9
// speedup vs baseline: 3.8072x; 2.0181x over previous
#include <cuda_runtime.h>
#include <cuda_fp16.h>
#include <math.h>

#define MAXN 100000
#define MAXG 1000
#define H  50
#define D3 15
#define D5 10
#define NC 6
#define EPS 1e-5f
#define TPB 128

// -------- scratch (device globals) --------
__device__ float g_x2sum[MAXN * 16];
__device__ float g_gsum[MAXG * 16];
__device__ float g_z[MAXG * D5];
__device__ float g_zstat[2 * D5];

// -------- helpers --------
__device__ __forceinline__ unsigned packh2(float a, float b) {
    __half2 h = __floats2half2_rn(a, b);
    return *reinterpret_cast<unsigned*>(&h);
}
__device__ __forceinline__ unsigned packh2_relu(float a, float b) {
    return packh2(fmaxf(a, 0.f), fmaxf(b, 0.f));
}
__device__ __forceinline__ void mma16(float c[4], unsigned a0, unsigned a1, unsigned a2, unsigned a3,
                                      unsigned b0, unsigned b1) {
    asm volatile("mma.sync.aligned.m16n8k16.row.col.f32.f16.f16.f32 "
        "{%0,%1,%2,%3}, {%4,%5,%6,%7}, {%8,%9}, {%0,%1,%2,%3};"
        : "+f"(c[0]), "+f"(c[1]), "+f"(c[2]), "+f"(c[3])
        : "r"(a0), "r"(a1), "r"(a2), "r"(a3), "r"(b0), "r"(b1));
}
__device__ __forceinline__ void red2(float* p, float a, float b) {
    asm volatile("red.global.add.v2.f32 [%0], {%1,%2};" :: "l"(p), "f"(a), "f"(b) : "memory");
}
__device__ __forceinline__ void red_add_v4(float* dst, float a, float b, float c, float d) {
    asm volatile("red.global.add.v4.f32 [%0], {%1,%2,%3,%4};"
                 :: "l"(dst), "f"(a), "f"(b), "f"(c), "f"(d) : "memory");
}

// -------------------- zero scratch --------------------
__global__ void zero_kernel(int n_x2, int n_g) {
    int i = blockIdx.x * blockDim.x + threadIdx.x;
    int stride = gridDim.x * blockDim.x;
    for (int k = i; k < n_x2; k += stride) g_x2sum[k] = 0.f;
    for (int k = i; k < n_g;  k += stride) g_gsum[k]  = 0.f;
    if (i < 2 * D5) g_zstat[i] = 0.f;
}

// -------------------- edge pipeline: fp16 m16n8k16, register-chained ------
__global__ __launch_bounds__(TPB, 3)
void edge_mma_kernel(const float* __restrict__ x, const int* __restrict__ ei,
                     const float* __restrict__ ea,
                     const float* __restrict__ ew1, const float* __restrict__ eb1,
                     const float* __restrict__ ew2, const float* __restrict__ eb2,
                     const float* __restrict__ nw1, const float* __restrict__ nb1,
                     const float* __restrict__ nw2, const float* __restrict__ nb2,
                     int E, int ntiles)
{
    // weights as packed half2 pairs along k: W[kpair][n]
    __shared__ unsigned uw1e[8 * 56];    // eW1: K=16 (9 real), N=56 (50 real)
    __shared__ unsigned uw2e[32 * 24];   // eW2: K=64 (50 real), N stride 24 (15 real)
    __shared__ unsigned uw1n[16 * 56];   // nW1 permuted: K=32 (rows: e2[15],0,xc[3],0..), N=56
    __shared__ unsigned uw2n[32 * 24];   // nW2: K=64, N stride 24 (15 real)
    __shared__ float sb1e[56], sb2e[16], sb1n[56], sb2n[16];
    __shared__ unsigned ustg[4 * 32 * 12];  // L1 input staging, stride 12 (conflict-free)

    int tid = threadIdx.x;

    // ---- weight preamble ----
    for (int i = tid; i < 8 * 56; i += TPB) {          // eW1
        int kp = i / 56, n = i % 56;
        int k0 = 2 * kp, k1 = 2 * kp + 1;
        float w0 = (k0 < 9 && n < 50) ? ew1[k0 * 50 + n] : 0.f;
        float w1 = (k1 < 9 && n < 50) ? ew1[k1 * 50 + n] : 0.f;
        uw1e[i] = packh2(w0, w1);
    }
    for (int i = tid; i < 32 * 24; i += TPB) {         // eW2
        int kp = i / 24, n = i % 24;
        int k0 = 2 * kp, k1 = k0 + 1;
        float w0 = (k0 < 50 && n < 15) ? ew2[k0 * 15 + n] : 0.f;
        float w1 = (k1 < 50 && n < 15) ? ew2[k1 * 15 + n] : 0.f;
        uw2e[i] = packh2(w0, w1);
    }
    for (int i = tid; i < 16 * 56; i += TPB) {         // nW1 permuted rows
        int kp = i / 56, n = i % 56;
        // feature row for k: k<15 -> nw1 row 3+k (e2), k==15 -> zero,
        // k in 16..18 -> nw1 row k-16 (xc), else zero
        float w[2];
        #pragma unroll
        for (int h = 0; h < 2; h++) {
            int k = 2 * kp + h;
            int src = (k < 15) ? (3 + k) : ((k >= 16 && k < 19) ? (k - 16) : -1);
            w[h] = (src >= 0 && n < 50) ? nw1[src * 50 + n] : 0.f;
        }
        uw1n[i] = packh2(w[0], w[1]);
    }
    for (int i = tid; i < 32 * 24; i += TPB) {         // nW2
        int kp = i / 24, n = i % 24;
        int k0 = 2 * kp, k1 = k0 + 1;
        float w0 = (k0 < 50 && n < 15) ? nw2[k0 * 15 + n] : 0.f;
        float w1 = (k1 < 50 && n < 15) ? nw2[k1 * 15 + n] : 0.f;
        uw2n[i] = packh2(w0, w1);
    }
    for (int i = tid; i < 56; i += TPB) sb1e[i] = (i < 50) ? eb1[i] : 0.f;
    for (int i = tid; i < 16; i += TPB) sb2e[i] = (i < 15) ? eb2[i] : 0.f;
    for (int i = tid; i < 56; i += TPB) sb1n[i] = (i < 50) ? nb1[i] : 0.f;
    for (int i = tid; i < 16; i += TPB) sb2n[i] = (i < 15) ? nb2[i] : 0.f;
    __syncthreads();

    int wid = tid >> 5, lane = tid & 31;
    int qid = lane >> 2, tq = lane & 3;
    unsigned* stg = ustg + wid * 384;        // [32 rows][stride 12]

    // zero the always-zero staging slots once
    stg[lane * 12 + 5] = 0u; stg[lane * 12 + 6] = 0u; stg[lane * 12 + 7] = 0u;
    __syncwarp();

    for (int t = blockIdx.x; t < ntiles; t += gridDim.x) {
        int wbase = t * 128 + wid * 32;
        int e = wbase + lane;
        int el = (e < E) ? e : (E - 1);
        int r = ei[el];
        int c = ei[E + el];
        float xr0 = __ldg(&x[3 * r]),  xr1 = __ldg(&x[3 * r + 1]),  xr2 = __ldg(&x[3 * r + 2]);
        float xc0 = __ldg(&x[3 * c]),  xc1 = __ldg(&x[3 * c + 1]),  xc2 = __ldg(&x[3 * c + 2]);
        float ea0 = ea[3 * el], ea1 = ea[3 * el + 1], ea2 = ea[3 * el + 2];

        // stage L1 input as half2: [xr0,xr1][xr2,xc0][xc1,xc2][ea0,ea1][ea2,0]
        {
            unsigned* sp = stg + lane * 12;
            sp[0] = packh2(xr0, xr1);
            sp[1] = packh2(xr2, xc0);
            sp[2] = packh2(xc1, xc2);
            sp[3] = packh2(ea0, ea1);
            sp[4] = packh2(ea2, 0.f);
        }
        __syncwarp();

        // ---- L1: in0[32,16] @ eW1[16,56] -> C1, relu -> A2 frags ----
        unsigned a2f[2][4][4];
        #pragma unroll
        for (int mt = 0; mt < 2; mt++) {
            unsigned a0 = stg[(16 * mt + qid) * 12 + tq];
            unsigned a1 = stg[(16 * mt + 8 + qid) * 12 + tq];
            unsigned a2 = stg[(16 * mt + qid) * 12 + tq + 4];
            unsigned a3 = stg[(16 * mt + 8 + qid) * 12 + tq + 4];
            float C1[7][4];
            #pragma unroll
            for (int nt = 0; nt < 7; nt++) {
                float bx = sb1e[8 * nt + 2 * tq], by = sb1e[8 * nt + 2 * tq + 1];
                C1[nt][0] = bx; C1[nt][1] = by; C1[nt][2] = bx; C1[nt][3] = by;
                unsigned b0 = uw1e[tq * 56 + 8 * nt + qid];
                unsigned b1 = uw1e[(tq + 4) * 56 + 8 * nt + qid];
                mma16(C1[nt], a0, a1, a2, a3, b0, b1);
            }
            #pragma unroll
            for (int kt = 0; kt < 4; kt++) {
                a2f[mt][kt][0] = packh2_relu(C1[2 * kt][0], C1[2 * kt][1]);
                a2f[mt][kt][1] = packh2_relu(C1[2 * kt][2], C1[2 * kt][3]);
                if (kt < 3) {
                    a2f[mt][kt][2] = packh2_relu(C1[2 * kt + 1][0], C1[2 * kt + 1][1]);
                    a2f[mt][kt][3] = packh2_relu(C1[2 * kt + 1][2], C1[2 * kt + 1][3]);
                } else {
                    a2f[mt][kt][2] = 0u; a2f[mt][kt][3] = 0u;
                }
            }
        }
        __syncwarp();   // staging reads done before next iter's writes

        // ---- L2: h[32,64] @ eW2[64,16] -> C2 (e2, no relu) ----
        float C2[2][2][4];
        #pragma unroll
        for (int mt = 0; mt < 2; mt++)
            #pragma unroll
            for (int nt = 0; nt < 2; nt++) {
                float bx = sb2e[8 * nt + 2 * tq], by = sb2e[8 * nt + 2 * tq + 1];
                float* cc = C2[mt][nt];
                cc[0] = bx; cc[1] = by; cc[2] = bx; cc[3] = by;
                #pragma unroll
                for (int kt = 0; kt < 4; kt++) {
                    unsigned b0 = uw2e[(kt * 8 + tq) * 24 + 8 * nt + qid];
                    unsigned b1 = uw2e[(kt * 8 + tq + 4) * 24 + 8 * nt + qid];
                    mma16(cc, a2f[mt][kt][0], a2f[mt][kt][1], a2f[mt][kt][2], a2f[mt][kt][3], b0, b1);
                }
            }

        // ---- build L3 A frags: kt0 = e2 (cvt), kt1 = xc via shuffles ----
        unsigned a3f[2][2][4];
        #pragma unroll
        for (int mt = 0; mt < 2; mt++) {
            a3f[mt][0][0] = packh2(C2[mt][0][0], C2[mt][0][1]);
            a3f[mt][0][1] = packh2(C2[mt][0][2], C2[mt][0][3]);
            a3f[mt][0][2] = packh2(C2[mt][1][0], C2[mt][1][1]);
            a3f[mt][0][3] = packh2(C2[mt][1][2], C2[mt][1][3]);
            int row0 = 16 * mt + qid, row1 = row0 + 8;
            float p0 = __shfl_sync(0xffffffffu, xc0, row0);
            float p1 = __shfl_sync(0xffffffffu, xc1, row0);
            float p2 = __shfl_sync(0xffffffffu, xc2, row0);
            float q0 = __shfl_sync(0xffffffffu, xc0, row1);
            float q1 = __shfl_sync(0xffffffffu, xc1, row1);
            float q2 = __shfl_sync(0xffffffffu, xc2, row1);
            unsigned a0 = (tq == 0) ? packh2(p0, p1) : ((tq == 1) ? packh2(p2, 0.f) : 0u);
            unsigned a1 = (tq == 0) ? packh2(q0, q1) : ((tq == 1) ? packh2(q2, 0.f) : 0u);
            a3f[mt][1][0] = a0; a3f[mt][1][1] = a1;
            a3f[mt][1][2] = 0u; a3f[mt][1][3] = 0u;
        }

        // ---- L3: nin[32,32] @ nW1'[32,56] -> C3, relu -> A4 frags ----
        // ---- L4: g[32,64] @ nW2[64,16] -> C4; scatter ----
        #pragma unroll
        for (int mt = 0; mt < 2; mt++) {
            float C3[7][4];
            #pragma unroll
            for (int nt = 0; nt < 7; nt++) {
                float bx = sb1n[8 * nt + 2 * tq], by = sb1n[8 * nt + 2 * tq + 1];
                C3[nt][0] = bx; C3[nt][1] = by; C3[nt][2] = bx; C3[nt][3] = by;
                #pragma unroll
                for (int kt = 0; kt < 2; kt++) {
                    unsigned b0 = uw1n[(kt * 8 + tq) * 56 + 8 * nt + qid];
                    unsigned b1 = uw1n[(kt * 8 + tq + 4) * 56 + 8 * nt + qid];
                    mma16(C3[nt], a3f[mt][kt][0], a3f[mt][kt][1], a3f[mt][kt][2], a3f[mt][kt][3], b0, b1);
                }
            }
            unsigned a4f[4][4];
            #pragma unroll
            for (int kt = 0; kt < 4; kt++) {
                a4f[kt][0] = packh2_relu(C3[2 * kt][0], C3[2 * kt][1]);
                a4f[kt][1] = packh2_relu(C3[2 * kt][2], C3[2 * kt][3]);
                if (kt < 3) {
                    a4f[kt][2] = packh2_relu(C3[2 * kt + 1][0], C3[2 * kt + 1][1]);
                    a4f[kt][3] = packh2_relu(C3[2 * kt + 1][2], C3[2 * kt + 1][3]);
                } else {
                    a4f[kt][2] = 0u; a4f[kt][3] = 0u;
                }
            }
            float C4[2][4];
            #pragma unroll
            for (int nt = 0; nt < 2; nt++) {
                float bx = sb2n[8 * nt + 2 * tq], by = sb2n[8 * nt + 2 * tq + 1];
                float* cc = C4[nt];
                cc[0] = bx; cc[1] = by; cc[2] = bx; cc[3] = by;
                #pragma unroll
                for (int kt = 0; kt < 4; kt++) {
                    unsigned b0 = uw2n[(kt * 8 + tq) * 24 + 8 * nt + qid];
                    unsigned b1 = uw2n[(kt * 8 + tq + 4) * 24 + 8 * nt + qid];
                    mma16(cc, a4f[kt][0], a4f[kt][1], a4f[kt][2], a4f[kt][3], b0, b1);
                }
            }
            // epilogue: rows qid (c0,c1) and qid+8 (c2,c3)
            #pragma unroll
            for (int rr = 0; rr < 2; rr++) {
                int row = mt * 16 + rr * 8 + qid;
                int rnode = __shfl_sync(0xffffffffu, r, row);
                if (wbase + row < E) {
                    float* dst = g_x2sum + (size_t)rnode * 16;
                    red2(dst + 2 * tq, C4[0][rr * 2 + 0], C4[0][rr * 2 + 1]);
                    float v1 = (tq == 3) ? 1.0f : C4[1][rr * 2 + 1];
                    red2(dst + 8 + 2 * tq, C4[1][rr * 2 + 0], v1);
                }
            }
        }
    }
}

// -------------------- node finalize + graph scatter --------------------
__global__ void node_kernel(const int* __restrict__ batch, int N)
{
    int n = blockIdx.x * blockDim.x + threadIdx.x;
    if (n >= N) return;
    const float* sp = g_x2sum + (size_t)n * 16;
    float inv = 1.f / fmaxf(sp[15], 1.f);
    float v[16];
    #pragma unroll
    for (int j = 0; j < D3; j++) v[j] = sp[j] * inv;
    v[15] = 1.0f;
    float* dst = g_gsum + (size_t)batch[n] * 16;
    red_add_v4(dst,      v[0],  v[1],  v[2],  v[3]);
    red_add_v4(dst + 4,  v[4],  v[5],  v[6],  v[7]);
    red_add_v4(dst + 8,  v[8],  v[9],  v[10], v[11]);
    red_add_v4(dst + 12, v[12], v[13], v[14], v[15]);
}

// -------------------- global MLP + fc1 + BN stats (warp per graph) -------
__global__ __launch_bounds__(256)
void global_kernel(const float* __restrict__ u,
                   const float* __restrict__ gw1, const float* __restrict__ gb1,
                   const float* __restrict__ gw2, const float* __restrict__ gb2,
                   const float* __restrict__ f1w, const float* __restrict__ f1b,
                   int G)
{
    __shared__ float sh[8][52];
    __shared__ float su[8][16];
    int w = threadIdx.x >> 5;
    int lane = threadIdx.x & 31;
    int gi = blockIdx.x * 8 + w;
    if (gi >= G) return;

    float gin[16];
    gin[0] = u[gi];
    const float* sp = g_gsum + (size_t)gi * 16;
    float inv = 1.f / fmaxf(__ldg(&sp[15]), 1.f);
    #pragma unroll
    for (int j = 0; j < D3; j++) gin[1 + j] = __ldg(&sp[j]) * inv;

    {
        int j = lane;
        float a = gb1[j];
        #pragma unroll
        for (int k = 0; k < 16; k++) a += gin[k] * gw1[k * H + j];
        sh[w][j] = fmaxf(a, 0.f);
        if (lane < H - 32) {
            int j2 = lane + 32;
            float a2 = gb1[j2];
            #pragma unroll
            for (int k = 0; k < 16; k++) a2 += gin[k] * gw1[k * H + j2];
            sh[w][j2] = fmaxf(a2, 0.f);
        }
    }
    __syncwarp();
    if (lane < D3) {
        float a = gb2[lane];
        #pragma unroll
        for (int k = 0; k < H; k++) a += sh[w][k] * gw2[k * D3 + lane];
        su[w][lane] = a;
    }
    __syncwarp();
    if (lane < D5) {
        float a = f1b[lane];
        #pragma unroll
        for (int k = 0; k < D3; k++) a += su[w][k] * f1w[k * D5 + lane];
        g_z[gi * D5 + lane] = a;
        atomicAdd(&g_zstat[lane], a);
        atomicAdd(&g_zstat[D5 + lane], a * a);
    }
}

// -------------------- BN + ReLU + fc2 + log_softmax --------------------
__global__ void head_kernel(const float* __restrict__ bn_g, const float* __restrict__ bn_b,
                            const float* __restrict__ f2w, const float* __restrict__ f2b,
                            float* __restrict__ out, int G)
{
    int gi = blockIdx.x * blockDim.x + threadIdx.x;
    if (gi >= G) return;
    float invG = 1.f / (float)G;
    float zr[D5];
    #pragma unroll
    for (int j = 0; j < D5; j++) {
        float mean = g_zstat[j] * invG;
        float var  = g_zstat[D5 + j] * invG - mean * mean;
        float zn = (g_z[gi * D5 + j] - mean) * rsqrtf(var + EPS) * bn_g[j] + bn_b[j];
        zr[j] = fmaxf(zn, 0.f);
    }
    float lg[NC];
    float mx = -1e30f;
    #pragma unroll
    for (int j = 0; j < NC; j++) {
        float a = f2b[j];
        #pragma unroll
        for (int k = 0; k < D5; k++) a += zr[k] * f2w[k * NC + j];
        lg[j] = a;
        mx = fmaxf(mx, a);
    }
    float se = 0.f;
    #pragma unroll
    for (int j = 0; j < NC; j++) se += expf(lg[j] - mx);
    float lse = mx + logf(se);
    #pragma unroll
    for (int j = 0; j < NC; j++) out[gi * NC + j] = lg[j] - lse;
}

// -------------------- launch --------------------
extern "C" void kernel_launch(void* const* d_in, const int* in_sizes, int n_in,
                              void* d_out, int out_size)
{
    const float* x     = (const float*)d_in[0];
    const int*   ei    = (const int*)  d_in[1];
    const float* ea    = (const float*)d_in[2];
    const float* u     = (const float*)d_in[3];
    const int*   batch = (const int*)  d_in[4];
    const float* ew1 = (const float*)d_in[5];
    const float* eb1 = (const float*)d_in[6];
    const float* ew2 = (const float*)d_in[7];
    const float* eb2 = (const float*)d_in[8];
    const float* nw1 = (const float*)d_in[9];
    const float* nb1 = (const float*)d_in[10];
    const float* nw2 = (const float*)d_in[11];
    const float* nb2 = (const float*)d_in[12];
    const float* gw1 = (const float*)d_in[13];
    const float* gb1 = (const float*)d_in[14];
    const float* gw2 = (const float*)d_in[15];
    const float* gb2 = (const float*)d_in[16];
    const float* f1w = (const float*)d_in[17];
    const float* f1b = (const float*)d_in[18];
    const float* bn_g = (const float*)d_in[19];
    const float* bn_b = (const float*)d_in[20];
    const float* f2w = (const float*)d_in[21];
    const float* f2b = (const float*)d_in[22];
    float* out = (float*)d_out;

    int N = in_sizes[0] / 3;
    int E = in_sizes[1] / 2;
    int G = in_sizes[3];

    {
        int n_x2 = N * 16, n_g = G * 16;
        int blocks = (n_x2 + 255) / 256;
        if (blocks > 4096) blocks = 4096;
        zero_kernel<<<blocks, 256>>>(n_x2, n_g);
    }
    {
        int ntiles = (E + 127) / 128;
        int blocks = 3 * 148;
        if (ntiles < blocks) blocks = ntiles;
        edge_mma_kernel<<<blocks, TPB>>>(x, ei, ea, ew1, eb1, ew2, eb2,
                                         nw1, nb1, nw2, nb2, E, ntiles);
    }
    node_kernel<<<(N + 255) / 256, 256>>>(batch, N);
    global_kernel<<<(G + 7) / 8, 256>>>(u, gw1, gb1, gw2, gb2, f1w, f1b, G);
    head_kernel<<<(G + 255) / 256, 256>>>(bn_g, bn_b, f2w, f2b, out, G);
}

// round 10
// speedup vs baseline: 4.0354x; 1.0599x over previous
#include <cuda_runtime.h>
#include <cuda_fp16.h>
#include <math.h>

#define MAXN 100000
#define MAXG 1000
#define H  50
#define D3 15
#define D5 10
#define NC 6
#define EPS 1e-5f
#define TPB 128

// -------- scratch (device globals) --------
__device__ float g_x2sum[MAXN * 16];
__device__ float g_gsum[MAXG * 16];
__device__ float g_z[MAXG * D5];
__device__ float g_zstat[2 * D5];
__device__ float g_x4[MAXN * 4];       // x padded to 4 floats/node

// -------- helpers --------
__device__ __forceinline__ unsigned packh2(float a, float b) {
    __half2 h = __floats2half2_rn(a, b);
    return *reinterpret_cast<unsigned*>(&h);
}
__device__ __forceinline__ unsigned packh2_relu(float a, float b) {
    return packh2(fmaxf(a, 0.f), fmaxf(b, 0.f));
}
__device__ __forceinline__ void mma16(float c[4], unsigned a0, unsigned a1, unsigned a2, unsigned a3,
                                      unsigned b0, unsigned b1) {
    asm volatile("mma.sync.aligned.m16n8k16.row.col.f32.f16.f16.f32 "
        "{%0,%1,%2,%3}, {%4,%5,%6,%7}, {%8,%9}, {%0,%1,%2,%3};"
        : "+f"(c[0]), "+f"(c[1]), "+f"(c[2]), "+f"(c[3])
        : "r"(a0), "r"(a1), "r"(a2), "r"(a3), "r"(b0), "r"(b1));
}
__device__ __forceinline__ void red_add_v4(float* dst, float a, float b, float c, float d) {
    asm volatile("red.global.add.v4.f32 [%0], {%1,%2,%3,%4};"
                 :: "l"(dst), "f"(a), "f"(b), "f"(c), "f"(d) : "memory");
}

// -------------------- zero scratch + pad x --------------------
__global__ void zero_kernel(const float* __restrict__ x, int N, int n_g) {
    int i = blockIdx.x * blockDim.x + threadIdx.x;
    int stride = gridDim.x * blockDim.x;
    int n_x2 = N * 16;
    for (int k = i; k < n_x2; k += stride) g_x2sum[k] = 0.f;
    for (int k = i; k < n_g;  k += stride) g_gsum[k]  = 0.f;
    int n_x4 = N * 4;
    for (int k = i; k < n_x4; k += stride) {
        int n = k >> 2, j = k & 3;
        g_x4[k] = (j < 3) ? x[n * 3 + j] : 0.f;
    }
    if (i < 2 * D5) g_zstat[i] = 0.f;
}

// -------------------- edge pipeline: fp16 m16n8k16, register-chained ------
__global__ __launch_bounds__(TPB, 3)
void edge_mma_kernel(const int* __restrict__ ei,
                     const float* __restrict__ ea,
                     const float* __restrict__ ew1, const float* __restrict__ eb1,
                     const float* __restrict__ ew2, const float* __restrict__ eb2,
                     const float* __restrict__ nw1, const float* __restrict__ nb1,
                     const float* __restrict__ nw2, const float* __restrict__ nb2,
                     int E, int ntiles)
{
    // weights as packed half2 pairs along k: W[kpair][n]
    __shared__ unsigned uw1e[8 * 56];    // eW1: K=16 (9 real), N=56 (50 real)
    __shared__ unsigned uw2e[32 * 24];   // eW2: K=64 (50 real), N stride 24 (15 real)
    __shared__ unsigned uw1n[16 * 56];   // nW1 permuted: K=32 (rows: e2[15],0,xc[3],0..), N=56
    __shared__ unsigned uw2n[32 * 24];   // nW2: K=64, N stride 24 (15 real)
    __shared__ float sb1e[56], sb2e[16], sb1n[56], sb2n[16];
    __shared__ unsigned ustg[4 * 32 * 12];  // L1 input staging, stride 12 (conflict-free)

    int tid = threadIdx.x;

    // ---- weight preamble ----
    for (int i = tid; i < 8 * 56; i += TPB) {          // eW1
        int kp = i / 56, n = i % 56;
        int k0 = 2 * kp, k1 = 2 * kp + 1;
        float w0 = (k0 < 9 && n < 50) ? ew1[k0 * 50 + n] : 0.f;
        float w1 = (k1 < 9 && n < 50) ? ew1[k1 * 50 + n] : 0.f;
        uw1e[i] = packh2(w0, w1);
    }
    for (int i = tid; i < 32 * 24; i += TPB) {         // eW2
        int kp = i / 24, n = i % 24;
        int k0 = 2 * kp, k1 = k0 + 1;
        float w0 = (k0 < 50 && n < 15) ? ew2[k0 * 15 + n] : 0.f;
        float w1 = (k1 < 50 && n < 15) ? ew2[k1 * 15 + n] : 0.f;
        uw2e[i] = packh2(w0, w1);
    }
    for (int i = tid; i < 16 * 56; i += TPB) {         // nW1 permuted rows
        int kp = i / 56, n = i % 56;
        float w[2];
        #pragma unroll
        for (int h = 0; h < 2; h++) {
            int k = 2 * kp + h;
            int src = (k < 15) ? (3 + k) : ((k >= 16 && k < 19) ? (k - 16) : -1);
            w[h] = (src >= 0 && n < 50) ? nw1[src * 50 + n] : 0.f;
        }
        uw1n[i] = packh2(w[0], w[1]);
    }
    for (int i = tid; i < 32 * 24; i += TPB) {         // nW2
        int kp = i / 24, n = i % 24;
        int k0 = 2 * kp, k1 = k0 + 1;
        float w0 = (k0 < 50 && n < 15) ? nw2[k0 * 15 + n] : 0.f;
        float w1 = (k1 < 50 && n < 15) ? nw2[k1 * 15 + n] : 0.f;
        uw2n[i] = packh2(w0, w1);
    }
    for (int i = tid; i < 56; i += TPB) sb1e[i] = (i < 50) ? eb1[i] : 0.f;
    for (int i = tid; i < 16; i += TPB) sb2e[i] = (i < 15) ? eb2[i] : 0.f;
    for (int i = tid; i < 56; i += TPB) sb1n[i] = (i < 50) ? nb1[i] : 0.f;
    for (int i = tid; i < 16; i += TPB) sb2n[i] = (i < 15) ? nb2[i] : 0.f;
    __syncthreads();

    int wid = tid >> 5, lane = tid & 31;
    int qid = lane >> 2, tq = lane & 3;
    unsigned* stg = ustg + wid * 384;        // [32 rows][stride 12]

    // zero the always-zero staging slots once
    stg[lane * 12 + 5] = 0u; stg[lane * 12 + 6] = 0u; stg[lane * 12 + 7] = 0u;
    __syncwarp();

    for (int t = blockIdx.x; t < ntiles; t += gridDim.x) {
        int wbase = t * 128 + wid * 32;
        int e = wbase + lane;
        int el = (e < E) ? e : (E - 1);
        int r = ei[el];
        int c = ei[E + el];
        float4 xr = *reinterpret_cast<const float4*>(g_x4 + 4 * (size_t)r);
        float4 xc4 = *reinterpret_cast<const float4*>(g_x4 + 4 * (size_t)c);
        float xc0 = xc4.x, xc1 = xc4.y, xc2 = xc4.z;
        float ea0 = ea[3 * el], ea1 = ea[3 * el + 1], ea2 = ea[3 * el + 2];

        // stage L1 input as half2: [xr0,xr1][xr2,xc0][xc1,xc2][ea0,ea1][ea2,0]
        {
            unsigned* sp = stg + lane * 12;
            sp[0] = packh2(xr.x, xr.y);
            sp[1] = packh2(xr.z, xc0);
            sp[2] = packh2(xc1, xc2);
            sp[3] = packh2(ea0, ea1);
            sp[4] = packh2(ea2, 0.f);
        }
        __syncwarp();

        // ---- L1: in0[32,16] @ eW1[16,56] -> C1, relu -> A2 frags ----
        unsigned a2f[2][4][4];
        #pragma unroll
        for (int mt = 0; mt < 2; mt++) {
            unsigned a0 = stg[(16 * mt + qid) * 12 + tq];
            unsigned a1 = stg[(16 * mt + 8 + qid) * 12 + tq];
            unsigned a2 = stg[(16 * mt + qid) * 12 + tq + 4];
            unsigned a3 = stg[(16 * mt + 8 + qid) * 12 + tq + 4];
            float C1[7][4];
            #pragma unroll
            for (int nt = 0; nt < 7; nt++) {
                float bx = sb1e[8 * nt + 2 * tq], by = sb1e[8 * nt + 2 * tq + 1];
                C1[nt][0] = bx; C1[nt][1] = by; C1[nt][2] = bx; C1[nt][3] = by;
                unsigned b0 = uw1e[tq * 56 + 8 * nt + qid];
                unsigned b1 = uw1e[(tq + 4) * 56 + 8 * nt + qid];
                mma16(C1[nt], a0, a1, a2, a3, b0, b1);
            }
            #pragma unroll
            for (int kt = 0; kt < 4; kt++) {
                a2f[mt][kt][0] = packh2_relu(C1[2 * kt][0], C1[2 * kt][1]);
                a2f[mt][kt][1] = packh2_relu(C1[2 * kt][2], C1[2 * kt][3]);
                if (kt < 3) {
                    a2f[mt][kt][2] = packh2_relu(C1[2 * kt + 1][0], C1[2 * kt + 1][1]);
                    a2f[mt][kt][3] = packh2_relu(C1[2 * kt + 1][2], C1[2 * kt + 1][3]);
                } else {
                    a2f[mt][kt][2] = 0u; a2f[mt][kt][3] = 0u;
                }
            }
        }
        __syncwarp();   // staging reads done before next iter's writes

        // ---- L2: h[32,64] @ eW2[64,16] -> C2 (e2, no relu) ----
        float C2[2][2][4];
        #pragma unroll
        for (int mt = 0; mt < 2; mt++)
            #pragma unroll
            for (int nt = 0; nt < 2; nt++) {
                float bx = sb2e[8 * nt + 2 * tq], by = sb2e[8 * nt + 2 * tq + 1];
                float* cc = C2[mt][nt];
                cc[0] = bx; cc[1] = by; cc[2] = bx; cc[3] = by;
                #pragma unroll
                for (int kt = 0; kt < 4; kt++) {
                    unsigned b0 = uw2e[(kt * 8 + tq) * 24 + 8 * nt + qid];
                    unsigned b1 = uw2e[(kt * 8 + tq + 4) * 24 + 8 * nt + qid];
                    mma16(cc, a2f[mt][kt][0], a2f[mt][kt][1], a2f[mt][kt][2], a2f[mt][kt][3], b0, b1);
                }
            }

        // ---- build L3 A frags: kt0 = e2 (cvt), kt1 = xc via shuffles ----
        unsigned a3f[2][2][4];
        #pragma unroll
        for (int mt = 0; mt < 2; mt++) {
            a3f[mt][0][0] = packh2(C2[mt][0][0], C2[mt][0][1]);
            a3f[mt][0][1] = packh2(C2[mt][0][2], C2[mt][0][3]);
            a3f[mt][0][2] = packh2(C2[mt][1][0], C2[mt][1][1]);
            a3f[mt][0][3] = packh2(C2[mt][1][2], C2[mt][1][3]);
            int row0 = 16 * mt + qid, row1 = row0 + 8;
            float p0 = __shfl_sync(0xffffffffu, xc0, row0);
            float p1 = __shfl_sync(0xffffffffu, xc1, row0);
            float p2 = __shfl_sync(0xffffffffu, xc2, row0);
            float q0 = __shfl_sync(0xffffffffu, xc0, row1);
            float q1 = __shfl_sync(0xffffffffu, xc1, row1);
            float q2 = __shfl_sync(0xffffffffu, xc2, row1);
            unsigned a0 = (tq == 0) ? packh2(p0, p1) : ((tq == 1) ? packh2(p2, 0.f) : 0u);
            unsigned a1 = (tq == 0) ? packh2(q0, q1) : ((tq == 1) ? packh2(q2, 0.f) : 0u);
            a3f[mt][1][0] = a0; a3f[mt][1][1] = a1;
            a3f[mt][1][2] = 0u; a3f[mt][1][3] = 0u;
        }

        // ---- L3 + L4 + v4 scatter ----
        #pragma unroll
        for (int mt = 0; mt < 2; mt++) {
            float C3[7][4];
            #pragma unroll
            for (int nt = 0; nt < 7; nt++) {
                float bx = sb1n[8 * nt + 2 * tq], by = sb1n[8 * nt + 2 * tq + 1];
                C3[nt][0] = bx; C3[nt][1] = by; C3[nt][2] = bx; C3[nt][3] = by;
                #pragma unroll
                for (int kt = 0; kt < 2; kt++) {
                    unsigned b0 = uw1n[(kt * 8 + tq) * 56 + 8 * nt + qid];
                    unsigned b1 = uw1n[(kt * 8 + tq + 4) * 56 + 8 * nt + qid];
                    mma16(C3[nt], a3f[mt][kt][0], a3f[mt][kt][1], a3f[mt][kt][2], a3f[mt][kt][3], b0, b1);
                }
            }
            unsigned a4f[4][4];
            #pragma unroll
            for (int kt = 0; kt < 4; kt++) {
                a4f[kt][0] = packh2_relu(C3[2 * kt][0], C3[2 * kt][1]);
                a4f[kt][1] = packh2_relu(C3[2 * kt][2], C3[2 * kt][3]);
                if (kt < 3) {
                    a4f[kt][2] = packh2_relu(C3[2 * kt + 1][0], C3[2 * kt + 1][1]);
                    a4f[kt][3] = packh2_relu(C3[2 * kt + 1][2], C3[2 * kt + 1][3]);
                } else {
                    a4f[kt][2] = 0u; a4f[kt][3] = 0u;
                }
            }
            float C4[2][4];
            #pragma unroll
            for (int nt = 0; nt < 2; nt++) {
                float bx = sb2n[8 * nt + 2 * tq], by = sb2n[8 * nt + 2 * tq + 1];
                float* cc = C4[nt];
                cc[0] = bx; cc[1] = by; cc[2] = bx; cc[3] = by;
                #pragma unroll
                for (int kt = 0; kt < 4; kt++) {
                    unsigned b0 = uw2n[(kt * 8 + tq) * 24 + 8 * nt + qid];
                    unsigned b1 = uw2n[(kt * 8 + tq + 4) * 24 + 8 * nt + qid];
                    mma16(cc, a4f[kt][0], a4f[kt][1], a4f[kt][2], a4f[kt][3], b0, b1);
                }
            }
            // epilogue: butterfly-pack to 4 consecutive floats per lane, one red.v4
            // even tq: cols [2tq .. 2tq+3]; odd tq: cols [6+2tq .. 9+2tq]
            #pragma unroll
            for (int rr = 0; rr < 2; rr++) {
                int row = mt * 16 + rr * 8 + qid;
                int rnode = __shfl_sync(0xffffffffu, r, row);
                float s0 = C4[0][rr * 2 + 0], s1 = C4[0][rr * 2 + 1];
                float s2 = C4[1][rr * 2 + 0], s3 = C4[1][rr * 2 + 1];
                float p0 = __shfl_xor_sync(0xffffffffu, s0, 1);
                float p1 = __shfl_xor_sync(0xffffffffu, s1, 1);
                float p2 = __shfl_xor_sync(0xffffffffu, s2, 1);
                float p3 = __shfl_xor_sync(0xffffffffu, s3, 1);
                bool odd = (tq & 1);
                float v0 = odd ? p2 : s0;
                float v1 = odd ? p3 : s1;
                float v2 = odd ? s2 : p0;
                float v3 = odd ? s3 : p1;
                if (tq == 3) v3 = 1.0f;              // count at col 15
                if (wbase + row < E) {
                    int off = odd ? (6 + 2 * tq) : (2 * tq);
                    red_add_v4(g_x2sum + (size_t)rnode * 16 + off, v0, v1, v2, v3);
                }
            }
        }
    }
}

// -------------------- node finalize + graph scatter --------------------
__global__ void node_kernel(const int* __restrict__ batch, int N)
{
    int n = blockIdx.x * blockDim.x + threadIdx.x;
    if (n >= N) return;
    const float* sp = g_x2sum + (size_t)n * 16;
    float inv = 1.f / fmaxf(sp[15], 1.f);
    float v[16];
    #pragma unroll
    for (int j = 0; j < D3; j++) v[j] = sp[j] * inv;
    v[15] = 1.0f;
    float* dst = g_gsum + (size_t)batch[n] * 16;
    red_add_v4(dst,      v[0],  v[1],  v[2],  v[3]);
    red_add_v4(dst + 4,  v[4],  v[5],  v[6],  v[7]);
    red_add_v4(dst + 8,  v[8],  v[9],  v[10], v[11]);
    red_add_v4(dst + 12, v[12], v[13], v[14], v[15]);
}

// -------------------- global MLP + fc1 + BN stats (warp per graph) -------
__global__ __launch_bounds__(256)
void global_kernel(const float* __restrict__ u,
                   const float* __restrict__ gw1, const float* __restrict__ gb1,
                   const float* __restrict__ gw2, const float* __restrict__ gb2,
                   const float* __restrict__ f1w, const float* __restrict__ f1b,
                   int G)
{
    __shared__ float sh[8][52];
    __shared__ float su[8][16];
    int w = threadIdx.x >> 5;
    int lane = threadIdx.x & 31;
    int gi = blockIdx.x * 8 + w;
    if (gi >= G) return;

    float gin[16];
    gin[0] = u[gi];
    const float* sp = g_gsum + (size_t)gi * 16;
    float inv = 1.f / fmaxf(__ldg(&sp[15]), 1.f);
    #pragma unroll
    for (int j = 0; j < D3; j++) gin[1 + j] = __ldg(&sp[j]) * inv;

    {
        int j = lane;
        float a = gb1[j];
        #pragma unroll
        for (int k = 0; k < 16; k++) a += gin[k] * gw1[k * H + j];
        sh[w][j] = fmaxf(a, 0.f);
        if (lane < H - 32) {
            int j2 = lane + 32;
            float a2 = gb1[j2];
            #pragma unroll
            for (int k = 0; k < 16; k++) a2 += gin[k] * gw1[k * H + j2];
            sh[w][j2] = fmaxf(a2, 0.f);
        }
    }
    __syncwarp();
    if (lane < D3) {
        float a = gb2[lane];
        #pragma unroll
        for (int k = 0; k < H; k++) a += sh[w][k] * gw2[k * D3 + lane];
        su[w][lane] = a;
    }
    __syncwarp();
    if (lane < D5) {
        float a = f1b[lane];
        #pragma unroll
        for (int k = 0; k < D3; k++) a += su[w][k] * f1w[k * D5 + lane];
        g_z[gi * D5 + lane] = a;
        atomicAdd(&g_zstat[lane], a);
        atomicAdd(&g_zstat[D5 + lane], a * a);
    }
}

// -------------------- BN + ReLU + fc2 + log_softmax --------------------
__global__ void head_kernel(const float* __restrict__ bn_g, const float* __restrict__ bn_b,
                            const float* __restrict__ f2w, const float* __restrict__ f2b,
                            float* __restrict__ out, int G)
{
    int gi = blockIdx.x * blockDim.x + threadIdx.x;
    if (gi >= G) return;
    float invG = 1.f / (float)G;
    float zr[D5];
    #pragma unroll
    for (int j = 0; j < D5; j++) {
        float mean = g_zstat[j] * invG;
        float var  = g_zstat[D5 + j] * invG - mean * mean;
        float zn = (g_z[gi * D5 + j] - mean) * rsqrtf(var + EPS) * bn_g[j] + bn_b[j];
        zr[j] = fmaxf(zn, 0.f);
    }
    float lg[NC];
    float mx = -1e30f;
    #pragma unroll
    for (int j = 0; j < NC; j++) {
        float a = f2b[j];
        #pragma unroll
        for (int k = 0; k < D5; k++) a += zr[k] * f2w[k * NC + j];
        lg[j] = a;
        mx = fmaxf(mx, a);
    }
    float se = 0.f;
    #pragma unroll
    for (int j = 0; j < NC; j++) se += expf(lg[j] - mx);
    float lse = mx + logf(se);
    #pragma unroll
    for (int j = 0; j < NC; j++) out[gi * NC + j] = lg[j] - lse;
}

// -------------------- launch --------------------
extern "C" void kernel_launch(void* const* d_in, const int* in_sizes, int n_in,
                              void* d_out, int out_size)
{
    const float* x     = (const float*)d_in[0];
    const int*   ei    = (const int*)  d_in[1];
    const float* ea    = (const float*)d_in[2];
    const float* u     = (const float*)d_in[3];
    const int*   batch = (const int*)  d_in[4];
    const float* ew1 = (const float*)d_in[5];
    const float* eb1 = (const float*)d_in[6];
    const float* ew2 = (const float*)d_in[7];
    const float* eb2 = (const float*)d_in[8];
    const float* nw1 = (const float*)d_in[9];
    const float* nb1 = (const float*)d_in[10];
    const float* nw2 = (const float*)d_in[11];
    const float* nb2 = (const float*)d_in[12];
    const float* gw1 = (const float*)d_in[13];
    const float* gb1 = (const float*)d_in[14];
    const float* gw2 = (const float*)d_in[15];
    const float* gb2 = (const float*)d_in[16];
    const float* f1w = (const float*)d_in[17];
    const float* f1b = (const float*)d_in[18];
    const float* bn_g = (const float*)d_in[19];
    const float* bn_b = (const float*)d_in[20];
    const float* f2w = (const float*)d_in[21];
    const float* f2b = (const float*)d_in[22];
    float* out = (float*)d_out;

    int N = in_sizes[0] / 3;
    int E = in_sizes[1] / 2;
    int G = in_sizes[3];

    {
        int n_x2 = N * 16;
        int blocks = (n_x2 + 255) / 256;
        if (blocks > 4096) blocks = 4096;
        zero_kernel<<<blocks, 256>>>(x, N, G * 16);
    }
    {
        int ntiles = (E + 127) / 128;
        int blocks = 3 * 148;
        if (ntiles < blocks) blocks = ntiles;
        edge_mma_kernel<<<blocks, TPB>>>(ei, ea, ew1, eb1, ew2, eb2,
                                         nw1, nb1, nw2, nb2, E, ntiles);
    }
    node_kernel<<<(N + 255) / 256, 256>>>(batch, N);
    global_kernel<<<(G + 7) / 8, 256>>>(u, gw1, gb1, gw2, gb2, f1w, f1b, G);
    head_kernel<<<(G + 255) / 256, 256>>>(bn_g, bn_b, f2w, f2b, out, G);
}

// round 13
// speedup vs baseline: 4.3424x; 1.0761x over previous
#include <cuda_runtime.h>
#include <cuda_fp16.h>
#include <math.h>

#define MAXN 100000
#define MAXG 1000
#define H  50
#define D3 15
#define D5 10
#define NC 6
#define EPS 1e-5f
#define TPB 128

// -------- scratch (device globals) --------
__device__ float g_x2sum[MAXN * 16];
__device__ float g_z[MAXG * D5];
__device__ float g_zstat[2 * D5];
__device__ float g_x4[MAXN * 4];
__device__ int   g_gstart[MAXG + 1];

// -------- helpers --------
__device__ __forceinline__ unsigned packh2(float a, float b) {
    __half2 h = __floats2half2_rn(a, b);
    return *reinterpret_cast<unsigned*>(&h);
}
__device__ __forceinline__ unsigned packh2_relu(float a, float b) {
    return packh2(fmaxf(a, 0.f), fmaxf(b, 0.f));
}
__device__ __forceinline__ void mma16(float c[4], unsigned a0, unsigned a1, unsigned a2, unsigned a3,
                                      unsigned b0, unsigned b1) {
    asm volatile("mma.sync.aligned.m16n8k16.row.col.f32.f16.f16.f32 "
        "{%0,%1,%2,%3}, {%4,%5,%6,%7}, {%8,%9}, {%0,%1,%2,%3};"
        : "+f"(c[0]), "+f"(c[1]), "+f"(c[2]), "+f"(c[3])
        : "r"(a0), "r"(a1), "r"(a2), "r"(a3), "r"(b0), "r"(b1));
}
__device__ __forceinline__ void red_add_v4(float* dst, float a, float b, float c, float d) {
    asm volatile("red.global.add.v4.f32 [%0], {%1,%2,%3,%4};"
                 :: "l"(dst), "f"(a), "f"(b), "f"(c), "f"(d) : "memory");
}

// -------------------- zero scratch + pad x + graph boundaries ------------
__global__ void zero_kernel(const float* __restrict__ x, const int* __restrict__ batch,
                            int N, int G) {
    int i = blockIdx.x * blockDim.x + threadIdx.x;
    int stride = gridDim.x * blockDim.x;
    float4 z4 = make_float4(0.f, 0.f, 0.f, 0.f);
    float4* x2v = reinterpret_cast<float4*>(g_x2sum);
    int n16 = N * 4;
    for (int k = i; k < n16; k += stride) x2v[k] = z4;
    for (int k = i; k < N; k += stride) {
        float4 v;
        v.x = x[3 * k]; v.y = x[3 * k + 1]; v.z = x[3 * k + 2]; v.w = 0.f;
        *reinterpret_cast<float4*>(g_x4 + 4 * (size_t)k) = v;
    }
    // g_gstart[g] = first node index n with batch[n] >= g (batch sorted)
    for (int k = i; k < N; k += stride) {
        int b = batch[k];
        int bn = (k + 1 < N) ? batch[k + 1] : G;
        if (k == 0)
            for (int g = 0; g <= b; g++) g_gstart[g] = 0;
        for (int g = b + 1; g <= bn; g++) g_gstart[g] = k + 1;
    }
    if (i < 2 * D5) g_zstat[i] = 0.f;
}

// -------------------- edge pipeline: fp16 m16n8k16, register-chained ------
__global__ __launch_bounds__(TPB, 3)
void edge_mma_kernel(const int* __restrict__ ei,
                     const float* __restrict__ ea,
                     const float* __restrict__ ew1, const float* __restrict__ eb1,
                     const float* __restrict__ ew2, const float* __restrict__ eb2,
                     const float* __restrict__ nw1, const float* __restrict__ nb1,
                     const float* __restrict__ nw2, const float* __restrict__ nb2,
                     int E, int ntiles)
{
    __shared__ unsigned uw1e[8 * 56];
    __shared__ unsigned uw2e[32 * 24];
    __shared__ unsigned uw1n[16 * 56];
    __shared__ unsigned uw2n[32 * 24];
    __shared__ float sb1e[56], sb2e[16], sb1n[56], sb2n[16];
    __shared__ unsigned ustg[4 * 32 * 12];

    int tid = threadIdx.x;

    for (int i = tid; i < 8 * 56; i += TPB) {
        int kp = i / 56, n = i % 56;
        int k0 = 2 * kp, k1 = 2 * kp + 1;
        float w0 = (k0 < 9 && n < 50) ? ew1[k0 * 50 + n] : 0.f;
        float w1 = (k1 < 9 && n < 50) ? ew1[k1 * 50 + n] : 0.f;
        uw1e[i] = packh2(w0, w1);
    }
    for (int i = tid; i < 32 * 24; i += TPB) {
        int kp = i / 24, n = i % 24;
        int k0 = 2 * kp, k1 = k0 + 1;
        float w0 = (k0 < 50 && n < 15) ? ew2[k0 * 15 + n] : 0.f;
        float w1 = (k1 < 50 && n < 15) ? ew2[k1 * 15 + n] : 0.f;
        uw2e[i] = packh2(w0, w1);
    }
    for (int i = tid; i < 16 * 56; i += TPB) {
        int kp = i / 56, n = i % 56;
        float w[2];
        #pragma unroll
        for (int h = 0; h < 2; h++) {
            int k = 2 * kp + h;
            int src = (k < 15) ? (3 + k) : ((k >= 16 && k < 19) ? (k - 16) : -1);
            w[h] = (src >= 0 && n < 50) ? nw1[src * 50 + n] : 0.f;
        }
        uw1n[i] = packh2(w[0], w[1]);
    }
    for (int i = tid; i < 32 * 24; i += TPB) {
        int kp = i / 24, n = i % 24;
        int k0 = 2 * kp, k1 = k0 + 1;
        float w0 = (k0 < 50 && n < 15) ? nw2[k0 * 15 + n] : 0.f;
        float w1 = (k1 < 50 && n < 15) ? nw2[k1 * 15 + n] : 0.f;
        uw2n[i] = packh2(w0, w1);
    }
    for (int i = tid; i < 56; i += TPB) sb1e[i] = (i < 50) ? eb1[i] : 0.f;
    for (int i = tid; i < 16; i += TPB) sb2e[i] = (i < 15) ? eb2[i] : 0.f;
    for (int i = tid; i < 56; i += TPB) sb1n[i] = (i < 50) ? nb1[i] : 0.f;
    for (int i = tid; i < 16; i += TPB) sb2n[i] = (i < 15) ? nb2[i] : 0.f;
    __syncthreads();

    int wid = tid >> 5, lane = tid & 31;
    int qid = lane >> 2, tq = lane & 3;
    unsigned* stg = ustg + wid * 384;

    stg[lane * 12 + 5] = 0u; stg[lane * 12 + 6] = 0u; stg[lane * 12 + 7] = 0u;
    __syncwarp();

    for (int t = blockIdx.x; t < ntiles; t += gridDim.x) {
        int wbase = t * 128 + wid * 32;
        int e = wbase + lane;
        int el = (e < E) ? e : (E - 1);
        int r = ei[el];
        int c = ei[E + el];
        float4 xr = *reinterpret_cast<const float4*>(g_x4 + 4 * (size_t)r);
        float4 xc4 = *reinterpret_cast<const float4*>(g_x4 + 4 * (size_t)c);
        float xc0 = xc4.x, xc1 = xc4.y, xc2 = xc4.z;
        float ea0 = ea[3 * el], ea1 = ea[3 * el + 1], ea2 = ea[3 * el + 2];

        {
            unsigned* sp = stg + lane * 12;
            sp[0] = packh2(xr.x, xr.y);
            sp[1] = packh2(xr.z, xc0);
            sp[2] = packh2(xc1, xc2);
            sp[3] = packh2(ea0, ea1);
            sp[4] = packh2(ea2, 0.f);
        }
        __syncwarp();

        // ---- L1 ----
        unsigned a2f[2][4][4];
        #pragma unroll
        for (int mt = 0; mt < 2; mt++) {
            unsigned a0 = stg[(16 * mt + qid) * 12 + tq];
            unsigned a1 = stg[(16 * mt + 8 + qid) * 12 + tq];
            unsigned a2 = stg[(16 * mt + qid) * 12 + tq + 4];
            unsigned a3 = stg[(16 * mt + 8 + qid) * 12 + tq + 4];
            float C1[7][4];
            #pragma unroll
            for (int nt = 0; nt < 7; nt++) {
                float bx = sb1e[8 * nt + 2 * tq], by = sb1e[8 * nt + 2 * tq + 1];
                C1[nt][0] = bx; C1[nt][1] = by; C1[nt][2] = bx; C1[nt][3] = by;
                unsigned b0 = uw1e[tq * 56 + 8 * nt + qid];
                unsigned b1 = uw1e[(tq + 4) * 56 + 8 * nt + qid];
                mma16(C1[nt], a0, a1, a2, a3, b0, b1);
            }
            #pragma unroll
            for (int kt = 0; kt < 4; kt++) {
                a2f[mt][kt][0] = packh2_relu(C1[2 * kt][0], C1[2 * kt][1]);
                a2f[mt][kt][1] = packh2_relu(C1[2 * kt][2], C1[2 * kt][3]);
                if (kt < 3) {
                    a2f[mt][kt][2] = packh2_relu(C1[2 * kt + 1][0], C1[2 * kt + 1][1]);
                    a2f[mt][kt][3] = packh2_relu(C1[2 * kt + 1][2], C1[2 * kt + 1][3]);
                } else {
                    a2f[mt][kt][2] = 0u; a2f[mt][kt][3] = 0u;
                }
            }
        }
        __syncwarp();

        // ---- L2 ----
        float C2[2][2][4];
        #pragma unroll
        for (int mt = 0; mt < 2; mt++)
            #pragma unroll
            for (int nt = 0; nt < 2; nt++) {
                float bx = sb2e[8 * nt + 2 * tq], by = sb2e[8 * nt + 2 * tq + 1];
                float* cc = C2[mt][nt];
                cc[0] = bx; cc[1] = by; cc[2] = bx; cc[3] = by;
                #pragma unroll
                for (int kt = 0; kt < 4; kt++) {
                    unsigned b0 = uw2e[(kt * 8 + tq) * 24 + 8 * nt + qid];
                    unsigned b1 = uw2e[(kt * 8 + tq + 4) * 24 + 8 * nt + qid];
                    mma16(cc, a2f[mt][kt][0], a2f[mt][kt][1], a2f[mt][kt][2], a2f[mt][kt][3], b0, b1);
                }
            }

        // ---- L3 A frags ----
        unsigned a3f[2][2][4];
        #pragma unroll
        for (int mt = 0; mt < 2; mt++) {
            a3f[mt][0][0] = packh2(C2[mt][0][0], C2[mt][0][1]);
            a3f[mt][0][1] = packh2(C2[mt][0][2], C2[mt][0][3]);
            a3f[mt][0][2] = packh2(C2[mt][1][0], C2[mt][1][1]);
            a3f[mt][0][3] = packh2(C2[mt][1][2], C2[mt][1][3]);
            int row0 = 16 * mt + qid, row1 = row0 + 8;
            float p0 = __shfl_sync(0xffffffffu, xc0, row0);
            float p1 = __shfl_sync(0xffffffffu, xc1, row0);
            float p2 = __shfl_sync(0xffffffffu, xc2, row0);
            float q0 = __shfl_sync(0xffffffffu, xc0, row1);
            float q1 = __shfl_sync(0xffffffffu, xc1, row1);
            float q2 = __shfl_sync(0xffffffffu, xc2, row1);
            unsigned a0 = (tq == 0) ? packh2(p0, p1) : ((tq == 1) ? packh2(p2, 0.f) : 0u);
            unsigned a1 = (tq == 0) ? packh2(q0, q1) : ((tq == 1) ? packh2(q2, 0.f) : 0u);
            a3f[mt][1][0] = a0; a3f[mt][1][1] = a1;
            a3f[mt][1][2] = 0u; a3f[mt][1][3] = 0u;
        }

        // ---- L3 + L4 + v4 scatter ----
        #pragma unroll
        for (int mt = 0; mt < 2; mt++) {
            float C3[7][4];
            #pragma unroll
            for (int nt = 0; nt < 7; nt++) {
                float bx = sb1n[8 * nt + 2 * tq], by = sb1n[8 * nt + 2 * tq + 1];
                C3[nt][0] = bx; C3[nt][1] = by; C3[nt][2] = bx; C3[nt][3] = by;
                #pragma unroll
                for (int kt = 0; kt < 2; kt++) {
                    unsigned b0 = uw1n[(kt * 8 + tq) * 56 + 8 * nt + qid];
                    unsigned b1 = uw1n[(kt * 8 + tq + 4) * 56 + 8 * nt + qid];
                    mma16(C3[nt], a3f[mt][kt][0], a3f[mt][kt][1], a3f[mt][kt][2], a3f[mt][kt][3], b0, b1);
                }
            }
            unsigned a4f[4][4];
            #pragma unroll
            for (int kt = 0; kt < 4; kt++) {
                a4f[kt][0] = packh2_relu(C3[2 * kt][0], C3[2 * kt][1]);
                a4f[kt][1] = packh2_relu(C3[2 * kt][2], C3[2 * kt][3]);
                if (kt < 3) {
                    a4f[kt][2] = packh2_relu(C3[2 * kt + 1][0], C3[2 * kt + 1][1]);
                    a4f[kt][3] = packh2_relu(C3[2 * kt + 1][2], C3[2 * kt + 1][3]);
                } else {
                    a4f[kt][2] = 0u; a4f[kt][3] = 0u;
                }
            }
            float C4[2][4];
            #pragma unroll
            for (int nt = 0; nt < 2; nt++) {
                float bx = sb2n[8 * nt + 2 * tq], by = sb2n[8 * nt + 2 * tq + 1];
                float* cc = C4[nt];
                cc[0] = bx; cc[1] = by; cc[2] = bx; cc[3] = by;
                #pragma unroll
                for (int kt = 0; kt < 4; kt++) {
                    unsigned b0 = uw2n[(kt * 8 + tq) * 24 + 8 * nt + qid];
                    unsigned b1 = uw2n[(kt * 8 + tq + 4) * 24 + 8 * nt + qid];
                    mma16(cc, a4f[kt][0], a4f[kt][1], a4f[kt][2], a4f[kt][3], b0, b1);
                }
            }
            #pragma unroll
            for (int rr = 0; rr < 2; rr++) {
                int row = mt * 16 + rr * 8 + qid;
                int rnode = __shfl_sync(0xffffffffu, r, row);
                float s0 = C4[0][rr * 2 + 0], s1 = C4[0][rr * 2 + 1];
                float s2 = C4[1][rr * 2 + 0], s3 = C4[1][rr * 2 + 1];
                float p0 = __shfl_xor_sync(0xffffffffu, s0, 1);
                float p1 = __shfl_xor_sync(0xffffffffu, s1, 1);
                float p2 = __shfl_xor_sync(0xffffffffu, s2, 1);
                float p3 = __shfl_xor_sync(0xffffffffu, s3, 1);
                bool odd = (tq & 1);
                float v0 = odd ? p2 : s0;
                float v1 = odd ? p3 : s1;
                float v2 = odd ? s2 : p0;
                float v3 = odd ? s3 : p1;
                if (tq == 3) v3 = 1.0f;
                if (wbase + row < E) {
                    int off = odd ? (6 + 2 * tq) : (2 * tq);
                    red_add_v4(g_x2sum + (size_t)rnode * 16 + off, v0, v1, v2, v3);
                }
            }
        }
    }
}

// ---------- fused: segmented node-mean + graph-mean + global MLP + fc1 ----
__global__ __launch_bounds__(256)
void graph_kernel(const float* __restrict__ u,
                  const float* __restrict__ gw1, const float* __restrict__ gb1,
                  const float* __restrict__ gw2, const float* __restrict__ gb2,
                  const float* __restrict__ f1w, const float* __restrict__ f1b,
                  int G)
{
    __shared__ float swg1[16 * 50];
    __shared__ float sbg1[50];
    __shared__ float swg2[50 * 15];
    __shared__ float sbg2[15];
    __shared__ float swf1[15 * 10];
    __shared__ float sbf1[10];
    __shared__ float sgin[8][16];
    __shared__ float sh[8][52];
    __shared__ float su[8][16];

    int tid = threadIdx.x;
    for (int i = tid; i < 800; i += 256) swg1[i] = gw1[i];
    for (int i = tid; i < 50;  i += 256) sbg1[i] = gb1[i];
    for (int i = tid; i < 750; i += 256) swg2[i] = gw2[i];
    for (int i = tid; i < 15;  i += 256) sbg2[i] = gb2[i];
    for (int i = tid; i < 150; i += 256) swf1[i] = f1w[i];
    for (int i = tid; i < 10;  i += 256) sbf1[i] = f1b[i];
    __syncthreads();

    int w = tid >> 5, lane = tid & 31;
    int gi = blockIdx.x * 8 + w;
    if (gi >= G) return;

    int lo = g_gstart[gi], hi = g_gstart[gi + 1];

    // segmented sum of x2 = msgsum/deg over this graph's nodes
    float acc[15];
    #pragma unroll
    for (int j = 0; j < 15; j++) acc[j] = 0.f;
    for (int n = lo + lane; n < hi; n += 32) {
        const float4* rp = reinterpret_cast<const float4*>(g_x2sum + (size_t)n * 16);
        float4 a = rp[0], b = rp[1], c = rp[2], d = rp[3];
        float inv = 1.f / fmaxf(d.w, 1.f);
        acc[0]  += a.x * inv; acc[1]  += a.y * inv; acc[2]  += a.z * inv; acc[3]  += a.w * inv;
        acc[4]  += b.x * inv; acc[5]  += b.y * inv; acc[6]  += b.z * inv; acc[7]  += b.w * inv;
        acc[8]  += c.x * inv; acc[9]  += c.y * inv; acc[10] += c.z * inv; acc[11] += c.w * inv;
        acc[12] += d.x * inv; acc[13] += d.y * inv; acc[14] += d.z * inv;
    }
    #pragma unroll
    for (int off = 16; off > 0; off >>= 1) {
        #pragma unroll
        for (int j = 0; j < 15; j++)
            acc[j] += __shfl_down_sync(0xffffffffu, acc[j], off);
    }
    if (lane == 0) {
        float invn = 1.f / fmaxf((float)(hi - lo), 1.f);
        sgin[w][0] = u[gi];
        #pragma unroll
        for (int j = 0; j < 15; j++) sgin[w][1 + j] = acc[j] * invn;
    }
    __syncwarp();

    float gin[16];
    #pragma unroll
    for (int k = 0; k < 16; k++) gin[k] = sgin[w][k];

    // layer1: 16 -> 50, relu (lanes j and j+32)
    {
        int j = lane;
        float a0 = sbg1[j], a1 = 0.f;
        #pragma unroll
        for (int k = 0; k < 16; k += 2) {
            a0 += gin[k]     * swg1[k * 50 + j];
            a1 += gin[k + 1] * swg1[(k + 1) * 50 + j];
        }
        sh[w][j] = fmaxf(a0 + a1, 0.f);
        if (lane < 18) {
            int j2 = lane + 32;
            float b0 = sbg1[j2], b1 = 0.f;
            #pragma unroll
            for (int k = 0; k < 16; k += 2) {
                b0 += gin[k]     * swg1[k * 50 + j2];
                b1 += gin[k + 1] * swg1[(k + 1) * 50 + j2];
            }
            sh[w][j2] = fmaxf(b0 + b1, 0.f);
        }
    }
    __syncwarp();
    // layer2: 50 -> 15
    if (lane < D3) {
        float a0 = sbg2[lane], a1 = 0.f;
        #pragma unroll
        for (int k = 0; k < 50; k += 2) {
            a0 += sh[w][k]     * swg2[k * D3 + lane];
            a1 += sh[w][k + 1] * swg2[(k + 1) * D3 + lane];
        }
        su[w][lane] = a0 + a1;
    }
    __syncwarp();
    // fc1: 15 -> 10 + BN stats
    if (lane < D5) {
        float a = sbf1[lane];
        #pragma unroll
        for (int k = 0; k < D3; k++) a += su[w][k] * swf1[k * D5 + lane];
        g_z[gi * D5 + lane] = a;
        atomicAdd(&g_zstat[lane], a);
        atomicAdd(&g_zstat[D5 + lane], a * a);
    }
}

// -------------------- BN + ReLU + fc2 + log_softmax --------------------
__global__ void head_kernel(const float* __restrict__ bn_g, const float* __restrict__ bn_b,
                            const float* __restrict__ f2w, const float* __restrict__ f2b,
                            float* __restrict__ out, int G)
{
    int gi = blockIdx.x * blockDim.x + threadIdx.x;
    if (gi >= G) return;
    float invG = 1.f / (float)G;
    float zr[D5];
    #pragma unroll
    for (int j = 0; j < D5; j++) {
        float mean = g_zstat[j] * invG;
        float var  = g_zstat[D5 + j] * invG - mean * mean;
        float zn = (g_z[gi * D5 + j] - mean) * rsqrtf(var + EPS) * bn_g[j] + bn_b[j];
        zr[j] = fmaxf(zn, 0.f);
    }
    float lg[NC];
    float mx = -1e30f;
    #pragma unroll
    for (int j = 0; j < NC; j++) {
        float a = f2b[j];
        #pragma unroll
        for (int k = 0; k < D5; k++) a += zr[k] * f2w[k * NC + j];
        lg[j] = a;
        mx = fmaxf(mx, a);
    }
    float se = 0.f;
    #pragma unroll
    for (int j = 0; j < NC; j++) se += expf(lg[j] - mx);
    float lse = mx + logf(se);
    #pragma unroll
    for (int j = 0; j < NC; j++) out[gi * NC + j] = lg[j] - lse;
}

// -------------------- launch --------------------
extern "C" void kernel_launch(void* const* d_in, const int* in_sizes, int n_in,
                              void* d_out, int out_size)
{
    const float* x     = (const float*)d_in[0];
    const int*   ei    = (const int*)  d_in[1];
    const float* ea    = (const float*)d_in[2];
    const float* u     = (const float*)d_in[3];
    const int*   batch = (const int*)  d_in[4];
    const float* ew1 = (const float*)d_in[5];
    const float* eb1 = (const float*)d_in[6];
    const float* ew2 = (const float*)d_in[7];
    const float* eb2 = (const float*)d_in[8];
    const float* nw1 = (const float*)d_in[9];
    const float* nb1 = (const float*)d_in[10];
    const float* nw2 = (const float*)d_in[11];
    const float* nb2 = (const float*)d_in[12];
    const float* gw1 = (const float*)d_in[13];
    const float* gb1 = (const float*)d_in[14];
    const float* gw2 = (const float*)d_in[15];
    const float* gb2 = (const float*)d_in[16];
    const float* f1w = (const float*)d_in[17];
    const float* f1b = (const float*)d_in[18];
    const float* bn_g = (const float*)d_in[19];
    const float* bn_b = (const float*)d_in[20];
    const float* f2w = (const float*)d_in[21];
    const float* f2b = (const float*)d_in[22];
    float* out = (float*)d_out;

    int N = in_sizes[0] / 3;
    int E = in_sizes[1] / 2;
    int G = in_sizes[3];

    {
        int work = N * 4;   // float4 count for x2sum clear dominates
        int blocks = (work + 255) / 256;
        if (blocks > 2048) blocks = 2048;
        zero_kernel<<<blocks, 256>>>(x, batch, N, G);
    }
    {
        int ntiles = (E + 127) / 128;
        int blocks = 3 * 148;
        if (ntiles < blocks) blocks = ntiles;
        edge_mma_kernel<<<blocks, TPB>>>(ei, ea, ew1, eb1, ew2, eb2,
                                         nw1, nb1, nw2, nb2, E, ntiles);
    }
    graph_kernel<<<(G + 7) / 8, 256>>>(u, gw1, gb1, gw2, gb2, f1w, f1b, G);
    head_kernel<<<(G + 255) / 256, 256>>>(bn_g, bn_b, f2w, f2b, out, G);
}